// round 2
// baseline (speedup 1.0000x reference)
#include <cuda_runtime.h>
#include <math.h>

// Problem constants
#define BB 64
#define TT 512
#define DD 512
#define UU 1024
#define G4 4096          // 4*UU
#define LN_EPS 1e-3f

// ---------------------------------------------------------------------------
// Scratch (device globals — no allocation allowed)
// ---------------------------------------------------------------------------
__device__ float g_zx[(size_t)BB * TT * G4];     // 512 MiB, reused by both layers
__device__ float g_hseq[(size_t)BB * TT * UU];   // 128 MiB, layer-1 h sequence (LN'd in place)
__device__ float g_hbuf0[BB * UU];
__device__ float g_hbuf1[BB * UU];
__device__ unsigned g_barcnt;

// ---------------------------------------------------------------------------
// GEMM: C[M,N] = A[M,K] @ W[K,N] + b[N]   (row-major, M%128==0, N%128==0, K%16==0)
// ---------------------------------------------------------------------------
#define BM 128
#define BN 128
#define BK 16

__global__ __launch_bounds__(256, 2)
void gemm_bias_kernel(const float* __restrict__ A, const float* __restrict__ W,
                      const float* __restrict__ b, float* __restrict__ C,
                      int M, int N, int K)
{
    __shared__ float As[BK][BM + 4];
    __shared__ float Ws[BK][BN + 4];

    const int tid = threadIdx.x;
    const int n0 = blockIdx.x * BN;
    const int m0 = blockIdx.y * BM;

    const int trow = (tid >> 4) << 3;
    const int tcol = (tid & 15) << 3;

    const int a_r = tid >> 2;
    const int a_c = (tid & 3) << 2;
    const int w_r = tid >> 5;
    const int w_c = (tid & 31) << 2;

    float acc[8][8];
    #pragma unroll
    for (int i = 0; i < 8; i++)
        #pragma unroll
        for (int j = 0; j < 8; j++) acc[i][j] = 0.f;

    for (int k0 = 0; k0 < K; k0 += BK) {
        #pragma unroll
        for (int h = 0; h < 2; h++) {
            int r = a_r + h * 64;
            float4 v = *(const float4*)&A[(size_t)(m0 + r) * K + k0 + a_c];
            As[a_c + 0][r] = v.x;
            As[a_c + 1][r] = v.y;
            As[a_c + 2][r] = v.z;
            As[a_c + 3][r] = v.w;
        }
        #pragma unroll
        for (int h = 0; h < 2; h++) {
            int r = w_r + h * 8;
            *(float4*)&Ws[r][w_c] = *(const float4*)&W[(size_t)(k0 + r) * N + n0 + w_c];
        }
        __syncthreads();

        #pragma unroll
        for (int kk = 0; kk < BK; kk++) {
            float am[8], wn[8];
            *(float4*)&am[0] = *(const float4*)&As[kk][trow];
            *(float4*)&am[4] = *(const float4*)&As[kk][trow + 4];
            *(float4*)&wn[0] = *(const float4*)&Ws[kk][tcol];
            *(float4*)&wn[4] = *(const float4*)&Ws[kk][tcol + 4];
            #pragma unroll
            for (int i = 0; i < 8; i++)
                #pragma unroll
                for (int j = 0; j < 8; j++)
                    acc[i][j] = fmaf(am[i], wn[j], acc[i][j]);
        }
        __syncthreads();
    }

    #pragma unroll
    for (int i = 0; i < 8; i++) {
        size_t base = (size_t)(m0 + trow + i) * N + n0 + tcol;
        #pragma unroll
        for (int j = 0; j < 8; j++)
            C[base + j] = acc[i][j] + b[n0 + tcol + j];
    }
}

// ---------------------------------------------------------------------------
// Software grid barrier (all 128 blocks are co-resident: 128 <= 148 SMs,
// 1 block/SM at 256 threads / 22KB smem).
// ---------------------------------------------------------------------------
__device__ __forceinline__ void grid_barrier(unsigned target)
{
    __threadfence();          // release this thread's __stcg h writes to L2
    __syncthreads();
    if (threadIdx.x == 0) {
        atomicAdd(&g_barcnt, 1u);
        while (*(volatile unsigned*)&g_barcnt < target) { }
    }
    __syncthreads();
    __threadfence();          // acquire before next step's __ldcg h reads
}

// ---------------------------------------------------------------------------
// Persistent LSTM layer: all TT timesteps in ONE launch.
// Grid: 128 blocks (8 units x 4 gates each), 256 threads.
// Per step: z = zx_t + h_in @ R ; gates ; c (in REGISTERS) ; h out.
// ---------------------------------------------------------------------------
__global__ __launch_bounds__(256, 1)
void lstm_layer_kernel(const float* __restrict__ zx,   // [B*TT][G4], row = b*TT + t
                       const float* __restrict__ R,    // [UU][G4]
                       float* __restrict__ hA,         // ping  (zeroed h0)
                       float* __restrict__ hB,         // pong
                       float* __restrict__ hseq)       // [B][TT][UU] or null
{
    __shared__ float hs[64][36];
    __shared__ float Rs[32][33];
    __shared__ float zs[64][33];

    const int tid = threadIdx.x;
    const int u0  = blockIdx.x * 8;
    const int tx  = tid & 31;      // col = gate*8 + j
    const int ty  = tid >> 5;

    // fixed gating ownership: items tid and tid+256  -> c lives in registers
    const int row0 = tid >> 3,          j0 = tid & 7;
    const int row1 = (tid + 256) >> 3,  j1 = tid & 7;
    float c0 = 0.f, c1 = 0.f;

    for (int t = 0; t < TT; t++) {
        const float* zx_t = zx + (size_t)t * G4;
        const float* hin  = (t & 1) ? hB : hA;
        float*       hout = (t & 1) ? hA : hB;

        float acc[8];
        #pragma unroll
        for (int r = 0; r < 8; r++) acc[r] = 0.f;

        for (int k0 = 0; k0 < UU; k0 += 32) {
            #pragma unroll
            for (int i = tid; i < 64 * 32; i += 256) {
                int r = i >> 5, kk = i & 31;
                hs[r][kk] = __ldcg(&hin[r * UU + k0 + kk]);   // L2-coherent read
            }
            #pragma unroll
            for (int i = tid; i < 32 * 32; i += 256) {
                int kk = i >> 5, cc = i & 31;
                Rs[kk][cc] = __ldg(&R[(size_t)(k0 + kk) * G4 + (cc >> 3) * UU + u0 + (cc & 7)]);
            }
            __syncthreads();

            #pragma unroll
            for (int kk = 0; kk < 32; kk += 4) {
                float q0 = Rs[kk + 0][tx];
                float q1 = Rs[kk + 1][tx];
                float q2 = Rs[kk + 2][tx];
                float q3 = Rs[kk + 3][tx];
                #pragma unroll
                for (int rr = 0; rr < 8; rr++) {
                    float4 hv = *(const float4*)&hs[ty * 8 + rr][kk];
                    float a = acc[rr];
                    a = fmaf(hv.x, q0, a);
                    a = fmaf(hv.y, q1, a);
                    a = fmaf(hv.z, q2, a);
                    a = fmaf(hv.w, q3, a);
                    acc[rr] = a;
                }
            }
            __syncthreads();
        }

        #pragma unroll
        for (int rr = 0; rr < 8; rr++)
            zs[ty * 8 + rr][tx] = acc[rr];
        __syncthreads();

        // ---- gating, item 0 ----
        {
            const float* zxr = zx_t + (size_t)row0 * (TT * G4);
            int u = u0 + j0;
            float zi = zs[row0][j0]      + __ldg(&zxr[u]);
            float zf = zs[row0][8 + j0]  + __ldg(&zxr[UU + u]);
            float zg = zs[row0][16 + j0] + __ldg(&zxr[2 * UU + u]);
            float zo = zs[row0][24 + j0] + __ldg(&zxr[3 * UU + u]);
            float ig = 1.f / (1.f + __expf(-zi));
            float fg = 1.f / (1.f + __expf(-zf));
            float og = 1.f / (1.f + __expf(-zo));
            c0 = fmaf(fg, c0, ig * zg);
            float hn = og * c0;
            __stcg(&hout[row0 * UU + u], hn);
            if (hseq) hseq[(size_t)row0 * (TT * UU) + (size_t)t * UU + u] = hn;
        }
        // ---- gating, item 1 ----
        {
            const float* zxr = zx_t + (size_t)row1 * (TT * G4);
            int u = u0 + j1;
            float zi = zs[row1][j1]      + __ldg(&zxr[u]);
            float zf = zs[row1][8 + j1]  + __ldg(&zxr[UU + u]);
            float zg = zs[row1][16 + j1] + __ldg(&zxr[2 * UU + u]);
            float zo = zs[row1][24 + j1] + __ldg(&zxr[3 * UU + u]);
            float ig = 1.f / (1.f + __expf(-zi));
            float fg = 1.f / (1.f + __expf(-zf));
            float og = 1.f / (1.f + __expf(-zo));
            c1 = fmaf(fg, c1, ig * zg);
            float hn = og * c1;
            __stcg(&hout[row1 * UU + u], hn);
            if (hseq) hseq[(size_t)row1 * (TT * UU) + (size_t)t * UU + u] = hn;
        }

        if (t != TT - 1)
            grid_barrier(128u * (unsigned)(t + 1));
    }
}

// ---------------------------------------------------------------------------
// LayerNorm (eps=1e-3) + tanh over last dim (UU=1024). One block per row.
// ---------------------------------------------------------------------------
__global__ __launch_bounds__(256, 4)
void ln_tanh_kernel(const float* __restrict__ in, float* __restrict__ out,
                    const float* __restrict__ gamma, const float* __restrict__ beta)
{
    const int row = blockIdx.x;
    const float* xr = in + (size_t)row * UU;
    float* yr = out + (size_t)row * UU;
    const int tid = threadIdx.x;

    float v[4];
    float s = 0.f, sq = 0.f;
    #pragma unroll
    for (int q = 0; q < 4; q++) {
        v[q] = xr[tid + q * 256];
        s += v[q];
        sq = fmaf(v[q], v[q], sq);
    }

    __shared__ float sm1[8], sm2[8];
    #pragma unroll
    for (int o = 16; o > 0; o >>= 1) {
        s  += __shfl_xor_sync(0xffffffffu, s, o);
        sq += __shfl_xor_sync(0xffffffffu, sq, o);
    }
    if ((tid & 31) == 0) { sm1[tid >> 5] = s; sm2[tid >> 5] = sq; }
    __syncthreads();
    __shared__ float s_mu, s_inv;
    if (tid == 0) {
        float ts = 0.f, tq = 0.f;
        #pragma unroll
        for (int w = 0; w < 8; w++) { ts += sm1[w]; tq += sm2[w]; }
        float mu = ts * (1.f / UU);
        float var = tq * (1.f / UU) - mu * mu;
        s_mu = mu;
        s_inv = rsqrtf(var + LN_EPS);
    }
    __syncthreads();
    float mu = s_mu, inv = s_inv;

    #pragma unroll
    for (int q = 0; q < 4; q++) {
        int idx = tid + q * 256;
        float y = (v[q] - mu) * inv * gamma[idx] + beta[idx];
        yr[idx] = tanhf(y);
    }
}

// ---------------------------------------------------------------------------
// Per-layer init: zero h0 (ping buffer) and reset the grid-barrier counter.
// ---------------------------------------------------------------------------
__global__ void init_kernel(float* __restrict__ h0)
{
    int i = blockIdx.x * blockDim.x + threadIdx.x;
    if (i == 0) g_barcnt = 0u;
    if (i < BB * UU) h0[i] = 0.f;
}

// ---------------------------------------------------------------------------
// Launch: 8 graph nodes total
// ---------------------------------------------------------------------------
extern "C" void kernel_launch(void* const* d_in, const int* in_sizes, int n_in,
                              void* d_out, int out_size)
{
    const float* x      = (const float*)d_in[0];
    const float* W1     = (const float*)d_in[1];
    const float* R1     = (const float*)d_in[2];
    const float* b1     = (const float*)d_in[3];
    const float* gamma1 = (const float*)d_in[4];
    const float* beta1  = (const float*)d_in[5];
    const float* W2     = (const float*)d_in[6];
    const float* R2     = (const float*)d_in[7];
    const float* b2     = (const float*)d_in[8];
    const float* gamma2 = (const float*)d_in[9];
    const float* beta2  = (const float*)d_in[10];
    float* out = (float*)d_out;

    float *zx, *hseq, *hb0, *hb1;
    cudaGetSymbolAddress((void**)&zx,   g_zx);
    cudaGetSymbolAddress((void**)&hseq, g_hseq);
    cudaGetSymbolAddress((void**)&hb0,  g_hbuf0);
    cudaGetSymbolAddress((void**)&hb1,  g_hbuf1);

    const int M = BB * TT;             // 32768
    const dim3 ggrid(G4 / BN, M / BM); // (32, 256)

    // ---- Layer 1 ----
    gemm_bias_kernel<<<ggrid, 256>>>(x, W1, b1, zx, M, G4, DD);
    init_kernel<<<(BB * UU + 255) / 256, 256>>>(hb0);
    lstm_layer_kernel<<<128, 256>>>(zx, R1, hb0, hb1, hseq);
    ln_tanh_kernel<<<M, 256>>>(hseq, hseq, gamma1, beta1);

    // ---- Layer 2 ----
    gemm_bias_kernel<<<ggrid, 256>>>(hseq, W2, b2, zx, M, G4, UU);
    init_kernel<<<(BB * UU + 255) / 256, 256>>>(hb0);
    lstm_layer_kernel<<<128, 256>>>(zx, R2, hb0, hb1, (float*)nullptr);
    // TT even -> final h (t=511, odd) was written to hA = hb0
    ln_tanh_kernel<<<BB, 256>>>(hb0, out, gamma2, beta2);
}

// round 4
// speedup vs baseline: 1.6363x; 1.6363x over previous
#include <cuda_runtime.h>
#include <math.h>
#include <stdint.h>

// Problem constants
#define BB 64
#define TT 512
#define DD 512
#define UU 1024
#define G4 4096          // 4*UU
#define LN_EPS 1e-3f

// ---------------------------------------------------------------------------
// Scratch (device globals — no allocation allowed)
// ---------------------------------------------------------------------------
__device__ float g_zx[(size_t)BB * TT * G4];     // 512 MiB, reused by both layers
__device__ float g_hseq[(size_t)BB * TT * UU];   // 128 MiB
__device__ float g_wt[(size_t)G4 * UU];          // 16 MiB, W^T scratch (reused)
__device__ float g_hbuf0[BB * UU];
__device__ float g_hbuf1[BB * UU];
__device__ __align__(128) unsigned g_barcnt[32]; // arrival counter (own line)
__device__ __align__(128) unsigned g_epoch[32];  // epoch flag (own line)

// ---------------------------------------------------------------------------
// Helpers
// ---------------------------------------------------------------------------
__device__ __forceinline__ float cvt_tf32(float a) {
    float r;
    asm("cvt.rna.tf32.f32 %0, %1;" : "=f"(r) : "f"(a));
    return r;
}

#define MMA_TF32(d, a, b0v, b1v) \
    asm volatile("mma.sync.aligned.m16n8k8.row.col.f32.tf32.tf32.f32 " \
        "{%0,%1,%2,%3}, {%4,%5,%6,%7}, {%8,%9}, {%0,%1,%2,%3};" \
        : "+f"((d)[0]), "+f"((d)[1]), "+f"((d)[2]), "+f"((d)[3]) \
        : "r"((a)[0]), "r"((a)[1]), "r"((a)[2]), "r"((a)[3]), \
          "r"(b0v), "r"(b1v))

// ===========================================================================
// Transpose: out[N][K] = in[K][N]
// ===========================================================================
__global__ __launch_bounds__(256)
void transpose_kernel(const float* __restrict__ in, float* __restrict__ out,
                      int K, int N)
{
    __shared__ float t[32][33];
    int bx = blockIdx.x * 32;   // N
    int by = blockIdx.y * 32;   // K
    int x = threadIdx.x, y = threadIdx.y;
    #pragma unroll
    for (int i = 0; i < 32; i += 8)
        t[y + i][x] = in[(size_t)(by + y + i) * N + bx + x];
    __syncthreads();
    #pragma unroll
    for (int i = 0; i < 32; i += 8)
        out[(size_t)(bx + y + i) * K + by + x] = t[x][y + i];
}

// ===========================================================================
// 3xTF32 mma.sync GEMM:  C[M,N] = A[M,K] @ W[K,N] + b,  Bt = W^T [N][K]
// Block 128x128, BK=32, 256 threads = 8 warps (4m x 2n), warp tile 32x64.
// Smem rows padded to 36 floats -> all fragment LDS conflict-free.
// ===========================================================================
#define TSZ (128 * 36)
#define GEMM_SMEM_BYTES (4 * TSZ * 4)

__global__ __launch_bounds__(256, 2)
void gemm_tf32_kernel(const float* __restrict__ A, const float* __restrict__ Bt,
                      const float* __restrict__ bias, float* __restrict__ C,
                      int M, int N, int K)
{
    extern __shared__ float sm[];
    float* As_hi = sm;
    float* As_lo = sm + TSZ;
    float* Bs_hi = sm + 2 * TSZ;
    float* Bs_lo = sm + 3 * TSZ;

    const int tid  = threadIdx.x;
    const int m0   = blockIdx.y * 128;
    const int n0   = blockIdx.x * 128;
    const int lane = tid & 31, wid = tid >> 5;
    const int wm   = (wid & 3) * 32;       // warp m offset
    const int wn   = (wid >> 2) * 64;      // warp n offset
    const int g    = lane >> 2, ii = lane & 3;

    float acc[2][8][4];
    #pragma unroll
    for (int mi = 0; mi < 2; mi++)
        #pragma unroll
        for (int ni = 0; ni < 8; ni++)
            #pragma unroll
            for (int q = 0; q < 4; q++) acc[mi][ni][q] = 0.f;

    for (int k0 = 0; k0 < K; k0 += 32) {
        __syncthreads();
        // stage A/B chunk (128 rows x 32 cols each) with tf32 hi/lo split
        #pragma unroll
        for (int p = 0; p < 4; p++) {
            int idx = p * 256 + tid;
            int r = idx >> 3, c = (idx & 7) * 4;
            {
                float4 v = __ldg((const float4*)&A[(size_t)(m0 + r) * K + k0 + c]);
                float4 hi, lo;
                hi.x = cvt_tf32(v.x); lo.x = cvt_tf32(v.x - hi.x);
                hi.y = cvt_tf32(v.y); lo.y = cvt_tf32(v.y - hi.y);
                hi.z = cvt_tf32(v.z); lo.z = cvt_tf32(v.z - hi.z);
                hi.w = cvt_tf32(v.w); lo.w = cvt_tf32(v.w - hi.w);
                *(float4*)&As_hi[r * 36 + c] = hi;
                *(float4*)&As_lo[r * 36 + c] = lo;
            }
            {
                float4 v = __ldg((const float4*)&Bt[(size_t)(n0 + r) * K + k0 + c]);
                float4 hi, lo;
                hi.x = cvt_tf32(v.x); lo.x = cvt_tf32(v.x - hi.x);
                hi.y = cvt_tf32(v.y); lo.y = cvt_tf32(v.y - hi.y);
                hi.z = cvt_tf32(v.z); lo.z = cvt_tf32(v.z - hi.z);
                hi.w = cvt_tf32(v.w); lo.w = cvt_tf32(v.w - hi.w);
                *(float4*)&Bs_hi[r * 36 + c] = hi;
                *(float4*)&Bs_lo[r * 36 + c] = lo;
            }
        }
        __syncthreads();

        #pragma unroll
        for (int ks = 0; ks < 4; ks++) {
            const int kb = ks * 8;
            uint32_t ah[2][4], al[2][4];
            #pragma unroll
            for (int mi = 0; mi < 2; mi++) {
                int r0 = (wm + mi * 16 + g) * 36 + kb;
                int r8 = (wm + mi * 16 + g + 8) * 36 + kb;
                ah[mi][0] = __float_as_uint(As_hi[r0 + ii]);
                ah[mi][1] = __float_as_uint(As_hi[r8 + ii]);
                ah[mi][2] = __float_as_uint(As_hi[r0 + ii + 4]);
                ah[mi][3] = __float_as_uint(As_hi[r8 + ii + 4]);
                al[mi][0] = __float_as_uint(As_lo[r0 + ii]);
                al[mi][1] = __float_as_uint(As_lo[r8 + ii]);
                al[mi][2] = __float_as_uint(As_lo[r0 + ii + 4]);
                al[mi][3] = __float_as_uint(As_lo[r8 + ii + 4]);
            }
            #pragma unroll
            for (int ni = 0; ni < 8; ni++) {
                int nb = (wn + ni * 8 + g) * 36 + kb;
                uint32_t bh0 = __float_as_uint(Bs_hi[nb + ii]);
                uint32_t bh1 = __float_as_uint(Bs_hi[nb + ii + 4]);
                uint32_t bl0 = __float_as_uint(Bs_lo[nb + ii]);
                uint32_t bl1 = __float_as_uint(Bs_lo[nb + ii + 4]);
                #pragma unroll
                for (int mi = 0; mi < 2; mi++) {
                    MMA_TF32(acc[mi][ni], ah[mi], bh0, bh1);
                    MMA_TF32(acc[mi][ni], ah[mi], bl0, bl1);
                    MMA_TF32(acc[mi][ni], al[mi], bh0, bh1);
                }
            }
        }
    }

    // epilogue: D frag layout -> rows (g, g+8), cols (2i, 2i+1)
    #pragma unroll
    for (int mi = 0; mi < 2; mi++) {
        int r0 = m0 + wm + mi * 16 + g;
        #pragma unroll
        for (int ni = 0; ni < 8; ni++) {
            int cc = n0 + wn + ni * 8 + ii * 2;
            float b0v = __ldg(&bias[cc]);
            float b1v = __ldg(&bias[cc + 1]);
            float2 o0 = make_float2(acc[mi][ni][0] + b0v, acc[mi][ni][1] + b1v);
            float2 o1 = make_float2(acc[mi][ni][2] + b0v, acc[mi][ni][3] + b1v);
            *(float2*)&C[(size_t)r0 * N + cc] = o0;
            *(float2*)&C[(size_t)(r0 + 8) * N + cc] = o1;
        }
    }
}

// ===========================================================================
// Fast grid barrier: release-atomic arrival, epoch flag on separate line,
// nanosleep-backoff acquire polling.
// ===========================================================================
__device__ __forceinline__ void grid_barrier_step(unsigned t1)
{
    __syncthreads();
    if (threadIdx.x == 0) {
        unsigned old;
        asm volatile("atom.release.gpu.global.add.u32 %0, [%1], %2;"
                     : "=r"(old) : "l"(&g_barcnt[0]), "r"(1u) : "memory");
        if (old + 1u == 128u * t1) {
            asm volatile("st.release.gpu.global.u32 [%0], %1;"
                         :: "l"(&g_epoch[0]), "r"(t1) : "memory");
        } else {
            unsigned e;
            do {
                __nanosleep(64);
                asm volatile("ld.acquire.gpu.global.u32 %0, [%1];"
                             : "=r"(e) : "l"(&g_epoch[0]) : "memory");
            } while (e < t1);
        }
    }
    __syncthreads();
}

// ===========================================================================
// Persistent LSTM layer (fp32 SIMT, double-buffered k-tiles, zx prefetch)
// 128 blocks x 256 threads; block owns 8 units x 4 gates for all 64 rows.
// ===========================================================================
__global__ __launch_bounds__(256, 1)
void lstm_layer_kernel(const float* __restrict__ zx,   // [B*TT][G4], row=b*TT+t
                       const float* __restrict__ R,    // [UU][G4]
                       float* __restrict__ hA, float* __restrict__ hB,
                       float* __restrict__ hseq)       // [B][TT][UU] or null
{
    __shared__ float hs[2][64][36];
    __shared__ float Rs[2][32][33];
    __shared__ float zs[64][33];

    const int tid = threadIdx.x;
    const int u0  = blockIdx.x * 8;
    const int tx  = tid & 31;
    const int ty  = tid >> 5;

    const int row0 = tid >> 3, j0 = tid & 7;
    const int row1 = row0 + 32;
    float c0 = 0.f, c1 = 0.f;

    for (int t = 0; t < TT; t++) {
        const float* hin  = (t & 1) ? hB : hA;
        float*       hout = (t & 1) ? hA : hB;

        // prefetch zx gate inputs for this step (independent of h)
        float zx0[4], zx1[4];
        {
            const float* z0 = zx + (size_t)row0 * (TT * G4) + (size_t)t * G4 + u0 + j0;
            const float* z1 = zx + (size_t)row1 * (TT * G4) + (size_t)t * G4 + u0 + j0;
            #pragma unroll
            for (int g = 0; g < 4; g++) { zx0[g] = __ldcs(z0 + g * UU); zx1[g] = __ldcs(z1 + g * UU); }
        }

        float acc[8];
        #pragma unroll
        for (int r = 0; r < 8; r++) acc[r] = 0.f;

        float hreg[8], rreg[4];
        // prologue: load tile 0
        #pragma unroll
        for (int q = 0; q < 8; q++) {
            int i = tid + q * 256; int r = i >> 5, kk = i & 31;
            hreg[q] = __ldcg(&hin[r * UU + kk]);
        }
        #pragma unroll
        for (int q = 0; q < 4; q++) {
            int i = tid + q * 256; int kk = i >> 5, cc = i & 31;
            rreg[q] = __ldg(&R[(size_t)kk * G4 + (cc >> 3) * UU + u0 + (cc & 7)]);
        }
        #pragma unroll
        for (int q = 0; q < 8; q++) { int i = tid + q * 256; hs[0][i >> 5][i & 31] = hreg[q]; }
        #pragma unroll
        for (int q = 0; q < 4; q++) { int i = tid + q * 256; Rs[0][i >> 5][i & 31] = rreg[q]; }
        __syncthreads();

        for (int kt = 0; kt < 32; kt++) {
            const int cur = kt & 1;
            if (kt < 31) {
                int k0 = (kt + 1) << 5;
                #pragma unroll
                for (int q = 0; q < 8; q++) {
                    int i = tid + q * 256; int r = i >> 5, kk = i & 31;
                    hreg[q] = __ldcg(&hin[r * UU + k0 + kk]);
                }
                #pragma unroll
                for (int q = 0; q < 4; q++) {
                    int i = tid + q * 256; int kk = i >> 5, cc = i & 31;
                    rreg[q] = __ldg(&R[(size_t)(k0 + kk) * G4 + (cc >> 3) * UU + u0 + (cc & 7)]);
                }
            }
            #pragma unroll
            for (int kk = 0; kk < 32; kk += 4) {
                float q0 = Rs[cur][kk + 0][tx];
                float q1 = Rs[cur][kk + 1][tx];
                float q2 = Rs[cur][kk + 2][tx];
                float q3 = Rs[cur][kk + 3][tx];
                #pragma unroll
                for (int rr = 0; rr < 8; rr++) {
                    float4 hv = *(const float4*)&hs[cur][ty * 8 + rr][kk];
                    float a = acc[rr];
                    a = fmaf(hv.x, q0, a);
                    a = fmaf(hv.y, q1, a);
                    a = fmaf(hv.z, q2, a);
                    a = fmaf(hv.w, q3, a);
                    acc[rr] = a;
                }
            }
            if (kt < 31) {
                const int nxt = cur ^ 1;
                #pragma unroll
                for (int q = 0; q < 8; q++) { int i = tid + q * 256; hs[nxt][i >> 5][i & 31] = hreg[q]; }
                #pragma unroll
                for (int q = 0; q < 4; q++) { int i = tid + q * 256; Rs[nxt][i >> 5][i & 31] = rreg[q]; }
            }
            __syncthreads();
        }

        #pragma unroll
        for (int rr = 0; rr < 8; rr++)
            zs[ty * 8 + rr][tx] = acc[rr];
        __syncthreads();

        // gating (c in registers)
        {
            int u = u0 + j0;
            float zi = zs[row0][j0]      + zx0[0];
            float zf = zs[row0][8 + j0]  + zx0[1];
            float zg = zs[row0][16 + j0] + zx0[2];
            float zo = zs[row0][24 + j0] + zx0[3];
            float ig = 1.f / (1.f + __expf(-zi));
            float fg = 1.f / (1.f + __expf(-zf));
            float og = 1.f / (1.f + __expf(-zo));
            c0 = fmaf(fg, c0, ig * zg);
            float hn = og * c0;
            __stcg(&hout[row0 * UU + u], hn);
            if (hseq) hseq[(size_t)row0 * (TT * UU) + (size_t)t * UU + u] = hn;
        }
        {
            int u = u0 + j0;
            float zi = zs[row1][j0]      + zx1[0];
            float zf = zs[row1][8 + j0]  + zx1[1];
            float zg = zs[row1][16 + j0] + zx1[2];
            float zo = zs[row1][24 + j0] + zx1[3];
            float ig = 1.f / (1.f + __expf(-zi));
            float fg = 1.f / (1.f + __expf(-zf));
            float og = 1.f / (1.f + __expf(-zo));
            c1 = fmaf(fg, c1, ig * zg);
            float hn = og * c1;
            __stcg(&hout[row1 * UU + u], hn);
            if (hseq) hseq[(size_t)row1 * (TT * UU) + (size_t)t * UU + u] = hn;
        }

        if (t != TT - 1)
            grid_barrier_step((unsigned)(t + 1));
    }
}

// ===========================================================================
// LayerNorm + tanh
// ===========================================================================
__global__ __launch_bounds__(256, 4)
void ln_tanh_kernel(const float* __restrict__ in, float* __restrict__ out,
                    const float* __restrict__ gamma, const float* __restrict__ beta)
{
    const int row = blockIdx.x;
    const float* xr = in + (size_t)row * UU;
    float* yr = out + (size_t)row * UU;
    const int tid = threadIdx.x;

    float v[4];
    float s = 0.f, sq = 0.f;
    #pragma unroll
    for (int q = 0; q < 4; q++) {
        v[q] = xr[tid + q * 256];
        s += v[q];
        sq = fmaf(v[q], v[q], sq);
    }
    __shared__ float sm1[8], sm2[8];
    #pragma unroll
    for (int o = 16; o > 0; o >>= 1) {
        s  += __shfl_xor_sync(0xffffffffu, s, o);
        sq += __shfl_xor_sync(0xffffffffu, sq, o);
    }
    if ((tid & 31) == 0) { sm1[tid >> 5] = s; sm2[tid >> 5] = sq; }
    __syncthreads();
    __shared__ float s_mu, s_inv;
    if (tid == 0) {
        float ts = 0.f, tq = 0.f;
        #pragma unroll
        for (int w = 0; w < 8; w++) { ts += sm1[w]; tq += sm2[w]; }
        float mu = ts * (1.f / UU);
        float var = tq * (1.f / UU) - mu * mu;
        s_mu = mu;
        s_inv = rsqrtf(var + LN_EPS);
    }
    __syncthreads();
    float mu = s_mu, inv = s_inv;
    #pragma unroll
    for (int q = 0; q < 4; q++) {
        int idx = tid + q * 256;
        float y = (v[q] - mu) * inv * gamma[idx] + beta[idx];
        yr[idx] = tanhf(y);
    }
}

// ===========================================================================
// Per-layer init: zero h0, reset barrier counter + epoch
// ===========================================================================
__global__ void init_kernel(float* __restrict__ h0)
{
    int i = blockIdx.x * blockDim.x + threadIdx.x;
    if (i == 0) { g_barcnt[0] = 0u; g_epoch[0] = 0u; }
    if (i < BB * UU) h0[i] = 0.f;
}

// ===========================================================================
// Launch: 10 graph nodes
// ===========================================================================
extern "C" void kernel_launch(void* const* d_in, const int* in_sizes, int n_in,
                              void* d_out, int out_size)
{
    const float* x      = (const float*)d_in[0];
    const float* W1     = (const float*)d_in[1];
    const float* R1     = (const float*)d_in[2];
    const float* b1     = (const float*)d_in[3];
    const float* gamma1 = (const float*)d_in[4];
    const float* beta1  = (const float*)d_in[5];
    const float* W2     = (const float*)d_in[6];
    const float* R2     = (const float*)d_in[7];
    const float* b2     = (const float*)d_in[8];
    const float* gamma2 = (const float*)d_in[9];
    const float* beta2  = (const float*)d_in[10];
    float* out = (float*)d_out;

    float *zx, *hseq, *wt, *hb0, *hb1;
    cudaGetSymbolAddress((void**)&zx,   g_zx);
    cudaGetSymbolAddress((void**)&hseq, g_hseq);
    cudaGetSymbolAddress((void**)&wt,   g_wt);
    cudaGetSymbolAddress((void**)&hb0,  g_hbuf0);
    cudaGetSymbolAddress((void**)&hb1,  g_hbuf1);

    cudaFuncSetAttribute(gemm_tf32_kernel,
                         cudaFuncAttributeMaxDynamicSharedMemorySize, GEMM_SMEM_BYTES);

    const int M = BB * TT;                       // 32768
    const dim3 ggrid(G4 / 128, M / 128);         // (32, 256)

    // ---- Layer 1 ----
    transpose_kernel<<<dim3(G4 / 32, DD / 32), dim3(32, 8)>>>(W1, wt, DD, G4);
    gemm_tf32_kernel<<<ggrid, 256, GEMM_SMEM_BYTES>>>(x, wt, b1, zx, M, G4, DD);
    init_kernel<<<(BB * UU + 255) / 256, 256>>>(hb0);
    lstm_layer_kernel<<<128, 256>>>(zx, R1, hb0, hb1, hseq);
    ln_tanh_kernel<<<M, 256>>>(hseq, hseq, gamma1, beta1);

    // ---- Layer 2 ----
    transpose_kernel<<<dim3(G4 / 32, UU / 32), dim3(32, 8)>>>(W2, wt, UU, G4);
    gemm_tf32_kernel<<<ggrid, 256, GEMM_SMEM_BYTES>>>(hseq, wt, b2, zx, M, G4, UU);
    init_kernel<<<(BB * UU + 255) / 256, 256>>>(hb0);
    lstm_layer_kernel<<<128, 256>>>(zx, R2, hb0, hb1, (float*)nullptr);
    // TT even -> final h was written to hA = hb0
    ln_tanh_kernel<<<BB, 256>>>(hb0, out, gamma2, beta2);
}

// round 6
// speedup vs baseline: 2.6647x; 1.6284x over previous
#include <cuda_runtime.h>
#include <math.h>
#include <stdint.h>

// Problem constants
#define BB 64
#define TT 512
#define DD 512
#define UU 1024
#define G4 4096          // 4*UU
#define LN_EPS 1e-3f

// ---------------------------------------------------------------------------
// Scratch (device globals — no allocation allowed)
// ---------------------------------------------------------------------------
__device__ float g_zx[(size_t)BB * TT * G4];     // 512 MiB, reused by both layers
__device__ float g_hseq[(size_t)BB * TT * UU];   // 128 MiB
__device__ float g_wt[(size_t)G4 * UU];          // 16 MiB, W^T scratch (reused)
__device__ float g_rp[(size_t)512 * 128 * 128];  // 32 MiB, packed R (B-frag layout)
// packed h (A-frag layout): [128 ktiles][4 mtiles][32 lanes][4 slots]
__device__ float g_hp_hi[2][128 * 4 * 32 * 4];   // ping/pong, 256KB each
__device__ float g_hp_lo[2][128 * 4 * 32 * 4];
__device__ float g_hlast[BB * UU];
__device__ __align__(128) unsigned g_barcnt[32]; // arrival counter (own line)
__device__ __align__(128) unsigned g_epoch[32];  // epoch flag (own line)

// ---------------------------------------------------------------------------
// Helpers
// ---------------------------------------------------------------------------
__device__ __forceinline__ float cvt_tf32(float a) {
    float r;
    asm("cvt.rna.tf32.f32 %0, %1;" : "=f"(r) : "f"(a));
    return r;
}

#define MMA_TF32(d, a, b0v, b1v) \
    asm volatile("mma.sync.aligned.m16n8k8.row.col.f32.tf32.tf32.f32 " \
        "{%0,%1,%2,%3}, {%4,%5,%6,%7}, {%8,%9}, {%0,%1,%2,%3};" \
        : "+f"((d)[0]), "+f"((d)[1]), "+f"((d)[2]), "+f"((d)[3]) \
        : "r"((a)[0]), "r"((a)[1]), "r"((a)[2]), "r"((a)[3]), \
          "r"(b0v), "r"(b1v))

#define MMA_T4(d, av, b0v, b1v) \
    asm volatile("mma.sync.aligned.m16n8k8.row.col.f32.tf32.tf32.f32 " \
        "{%0,%1,%2,%3}, {%4,%5,%6,%7}, {%8,%9}, {%0,%1,%2,%3};" \
        : "+f"((d)[0]), "+f"((d)[1]), "+f"((d)[2]), "+f"((d)[3]) \
        : "r"(__float_as_uint((av).x)), "r"(__float_as_uint((av).y)), \
          "r"(__float_as_uint((av).z)), "r"(__float_as_uint((av).w)), \
          "r"(__float_as_uint(b0v)), "r"(__float_as_uint(b1v)))

// ===========================================================================
// Transpose: out[N][K] = in[K][N]
// ===========================================================================
__global__ __launch_bounds__(256)
void transpose_kernel(const float* __restrict__ in, float* __restrict__ out,
                      int K, int N)
{
    __shared__ float t[32][33];
    int bx = blockIdx.x * 32;   // N
    int by = blockIdx.y * 32;   // K
    int x = threadIdx.x, y = threadIdx.y;
    #pragma unroll
    for (int i = 0; i < 32; i += 8)
        t[y + i][x] = in[(size_t)(by + y + i) * N + bx + x];
    __syncthreads();
    #pragma unroll
    for (int i = 0; i < 32; i += 8)
        out[(size_t)(bx + y + i) * K + by + x] = t[x][y + i];
}

// ===========================================================================
// Pack R into B-fragment layout with tf32 hi/lo split.
// Rp[nt][kt][lane] = float4(bh0, bh1, bl0, bl1)
//   bh0/bl0 from R[kt*8 + lane%4][nt*8 + lane/4]
//   bh1/bl1 from R[kt*8 + 4 + lane%4][nt*8 + lane/4]
// ===========================================================================
__global__ __launch_bounds__(256)
void pack_r_kernel(const float* __restrict__ R, float* __restrict__ Rp)
{
    int gw = (blockIdx.x * blockDim.x + threadIdx.x) >> 5;
    int lane = threadIdx.x & 31;
    int nt = gw >> 7;          // 0..511
    int kt = gw & 127;         // 0..127
    int col = nt * 8 + (lane >> 2);
    int r0  = kt * 8 + (lane & 3);
    float v0 = __ldg(&R[(size_t)r0 * G4 + col]);
    float v1 = __ldg(&R[(size_t)(r0 + 4) * G4 + col]);
    float4 o;
    o.x = cvt_tf32(v0); o.z = cvt_tf32(v0 - o.x);
    o.y = cvt_tf32(v1); o.w = cvt_tf32(v1 - o.y);
    *(float4*)&Rp[((size_t)(nt * 128 + kt) * 32 + lane) * 4] = o;
}

// ===========================================================================
// 3xTF32 mma.sync GEMM (unchanged from R4):  C = A @ W + b, Bt = W^T
// ===========================================================================
#define TSZ (128 * 36)
#define GEMM_SMEM_BYTES (4 * TSZ * 4)

__global__ __launch_bounds__(256, 2)
void gemm_tf32_kernel(const float* __restrict__ A, const float* __restrict__ Bt,
                      const float* __restrict__ bias, float* __restrict__ C,
                      int M, int N, int K)
{
    extern __shared__ float sm[];
    float* As_hi = sm;
    float* As_lo = sm + TSZ;
    float* Bs_hi = sm + 2 * TSZ;
    float* Bs_lo = sm + 3 * TSZ;

    const int tid  = threadIdx.x;
    const int m0   = blockIdx.y * 128;
    const int n0   = blockIdx.x * 128;
    const int lane = tid & 31, wid = tid >> 5;
    const int wm   = (wid & 3) * 32;
    const int wn   = (wid >> 2) * 64;
    const int g    = lane >> 2, ii = lane & 3;

    float acc[2][8][4];
    #pragma unroll
    for (int mi = 0; mi < 2; mi++)
        #pragma unroll
        for (int ni = 0; ni < 8; ni++)
            #pragma unroll
            for (int q = 0; q < 4; q++) acc[mi][ni][q] = 0.f;

    for (int k0 = 0; k0 < K; k0 += 32) {
        __syncthreads();
        #pragma unroll
        for (int p = 0; p < 4; p++) {
            int idx = p * 256 + tid;
            int r = idx >> 3, c = (idx & 7) * 4;
            {
                float4 v = __ldg((const float4*)&A[(size_t)(m0 + r) * K + k0 + c]);
                float4 hi, lo;
                hi.x = cvt_tf32(v.x); lo.x = cvt_tf32(v.x - hi.x);
                hi.y = cvt_tf32(v.y); lo.y = cvt_tf32(v.y - hi.y);
                hi.z = cvt_tf32(v.z); lo.z = cvt_tf32(v.z - hi.z);
                hi.w = cvt_tf32(v.w); lo.w = cvt_tf32(v.w - hi.w);
                *(float4*)&As_hi[r * 36 + c] = hi;
                *(float4*)&As_lo[r * 36 + c] = lo;
            }
            {
                float4 v = __ldg((const float4*)&Bt[(size_t)(n0 + r) * K + k0 + c]);
                float4 hi, lo;
                hi.x = cvt_tf32(v.x); lo.x = cvt_tf32(v.x - hi.x);
                hi.y = cvt_tf32(v.y); lo.y = cvt_tf32(v.y - hi.y);
                hi.z = cvt_tf32(v.z); lo.z = cvt_tf32(v.z - hi.z);
                hi.w = cvt_tf32(v.w); lo.w = cvt_tf32(v.w - hi.w);
                *(float4*)&Bs_hi[r * 36 + c] = hi;
                *(float4*)&Bs_lo[r * 36 + c] = lo;
            }
        }
        __syncthreads();

        #pragma unroll
        for (int ks = 0; ks < 4; ks++) {
            const int kb = ks * 8;
            uint32_t ah[2][4], al[2][4];
            #pragma unroll
            for (int mi = 0; mi < 2; mi++) {
                int r0 = (wm + mi * 16 + g) * 36 + kb;
                int r8 = (wm + mi * 16 + g + 8) * 36 + kb;
                ah[mi][0] = __float_as_uint(As_hi[r0 + ii]);
                ah[mi][1] = __float_as_uint(As_hi[r8 + ii]);
                ah[mi][2] = __float_as_uint(As_hi[r0 + ii + 4]);
                ah[mi][3] = __float_as_uint(As_hi[r8 + ii + 4]);
                al[mi][0] = __float_as_uint(As_lo[r0 + ii]);
                al[mi][1] = __float_as_uint(As_lo[r8 + ii]);
                al[mi][2] = __float_as_uint(As_lo[r0 + ii + 4]);
                al[mi][3] = __float_as_uint(As_lo[r8 + ii + 4]);
            }
            #pragma unroll
            for (int ni = 0; ni < 8; ni++) {
                int nb = (wn + ni * 8 + g) * 36 + kb;
                uint32_t bh0 = __float_as_uint(Bs_hi[nb + ii]);
                uint32_t bh1 = __float_as_uint(Bs_hi[nb + ii + 4]);
                uint32_t bl0 = __float_as_uint(Bs_lo[nb + ii]);
                uint32_t bl1 = __float_as_uint(Bs_lo[nb + ii + 4]);
                #pragma unroll
                for (int mi = 0; mi < 2; mi++) {
                    MMA_TF32(acc[mi][ni], ah[mi], bh0, bh1);
                    MMA_TF32(acc[mi][ni], ah[mi], bl0, bl1);
                    MMA_TF32(acc[mi][ni], al[mi], bh0, bh1);
                }
            }
        }
    }

    #pragma unroll
    for (int mi = 0; mi < 2; mi++) {
        int r0 = m0 + wm + mi * 16 + g;
        #pragma unroll
        for (int ni = 0; ni < 8; ni++) {
            int cc = n0 + wn + ni * 8 + ii * 2;
            float b0v = __ldg(&bias[cc]);
            float b1v = __ldg(&bias[cc + 1]);
            float2 o0 = make_float2(acc[mi][ni][0] + b0v, acc[mi][ni][1] + b1v);
            float2 o1 = make_float2(acc[mi][ni][2] + b0v, acc[mi][ni][3] + b1v);
            *(float2*)&C[(size_t)r0 * N + cc] = o0;
            *(float2*)&C[(size_t)(r0 + 8) * N + cc] = o1;
        }
    }
}

// ===========================================================================
// Fast grid barrier
// ===========================================================================
__device__ __forceinline__ void grid_barrier_step(unsigned t1)
{
    __syncthreads();
    if (threadIdx.x == 0) {
        unsigned old;
        asm volatile("atom.release.gpu.global.add.u32 %0, [%1], %2;"
                     : "=r"(old) : "l"(&g_barcnt[0]), "r"(1u) : "memory");
        if (old + 1u == 128u * t1) {
            asm volatile("st.release.gpu.global.u32 [%0], %1;"
                         :: "l"(&g_epoch[0]), "r"(t1) : "memory");
        } else {
            unsigned e;
            do {
                __nanosleep(64);
                asm volatile("ld.acquire.gpu.global.u32 %0, [%1];"
                             : "=r"(e) : "l"(&g_epoch[0]) : "memory");
            } while (e < t1);
        }
    }
    __syncthreads();
}

// ===========================================================================
// Persistent LSTM layer with mma.sync recurrence.
// 128 blocks x 256 threads. Block: m64 x n32 (units u0=b*8, 4 gates).
// Warp (wm 0..3, wn 0..1): tile m16 x n16, full K=1024, 3xTF32.
// h in packed A-frag layout (ping/pong), R in packed B-frag layout.
// ===========================================================================
__global__ __launch_bounds__(256, 1)
void lstm_mma_kernel(const float* __restrict__ zx,     // [B*TT][G4], row=b*TT+t
                     const float* __restrict__ Rp,     // packed
                     float* __restrict__ hpH0, float* __restrict__ hpL0,
                     float* __restrict__ hpH1, float* __restrict__ hpL1,
                     float* __restrict__ hseq,         // [B][TT][UU] or null
                     float* __restrict__ hlast)        // [B][UU] or null
{
    extern __shared__ float As[];      // 16384 floats: hi[0:8192), lo[8192:16384)
    __shared__ float zs[64][33];

    const int tid  = threadIdx.x;
    const int b    = blockIdx.x;       // 0..127
    const int u0   = b * 8;
    const int lane = tid & 31, wid = tid >> 5;
    const int wm   = wid & 3;          // m-tile 0..3
    const int wn   = wid >> 2;         // 0..1 -> gates 2wn, 2wn+1
    const int lane4 = lane * 4;

    // B-frag base offsets (floats): ntile = gate*128 + b
    const float* Bp0 = Rp + (size_t)((2 * wn) * 128 + b) * 16384;
    const float* Bp1 = Rp + (size_t)((2 * wn + 1) * 128 + b) * 16384;

    // gating ownership
    const int row0 = tid >> 3, j0 = tid & 7;
    const int row1 = row0 + 32;
    float c0 = 0.f, c1 = 0.f;

    // precomputed packed-write indices for gating
    auto pidx = [&](int row) {
        int mt = row >> 4, mm = row & 15;
        int lw = (mm & 7) * 4 + (j0 & 3);
        int slot = ((mm >> 3) & 1) + ((j0 >> 2) << 1);
        return (b * 4 + mt) * 128 + lw * 4 + slot;
    };
    const int pw0 = pidx(row0);
    const int pw1 = pidx(row1);

    for (int t = 0; t < TT; t++) {
        const float* AhIn = (t & 1) ? hpH1 : hpH0;
        const float* AlIn = (t & 1) ? hpL1 : hpL0;
        float* AhOut = (t & 1) ? hpH0 : hpH1;
        float* AlOut = (t & 1) ? hpL0 : hpL1;

        // zx prefetch (gate inputs, independent of h)
        float zx0[4], zx1[4];
        {
            const float* z0 = zx + (size_t)row0 * (TT * G4) + (size_t)t * G4 + u0 + j0;
            const float* z1 = zx + (size_t)row1 * (TT * G4) + (size_t)t * G4 + u0 + j0;
            #pragma unroll
            for (int g = 0; g < 4; g++) { zx0[g] = __ldcs(z0 + g * UU); zx1[g] = __ldcs(z1 + g * UU); }
        }

        float acc0[4] = {0.f, 0.f, 0.f, 0.f};
        float acc1[4] = {0.f, 0.f, 0.f, 0.f};

        // 8 chunks of 16 ktiles (k=128 each)
        for (int ch = 0; ch < 8; ch++) {
            __syncthreads();   // protect As reuse
            // stage A chunk: 8192 floats hi + 8192 lo (L2 reads; L1 stale across barrier)
            const float4* srcH = (const float4*)(AhIn + ch * 8192);
            const float4* srcL = (const float4*)(AlIn + ch * 8192);
            float4* dstH = (float4*)As;
            float4* dstL = (float4*)(As + 8192);
            #pragma unroll
            for (int q = 0; q < 8; q++) {
                dstH[q * 256 + tid] = __ldcg(&srcH[q * 256 + tid]);
                dstL[q * 256 + tid] = __ldcg(&srcL[q * 256 + tid]);
            }
            __syncthreads();

            #pragma unroll
            for (int kt = 0; kt < 16; kt++) {
                const int ao = (kt * 4 + wm) * 128 + lane4;
                float4 ah = *(const float4*)&As[ao];
                float4 al = *(const float4*)&As[8192 + ao];
                const int ktg = ch * 16 + kt;
                float4 b0 = __ldcg((const float4*)(Bp0 + (size_t)ktg * 128 + lane4));
                float4 b1 = __ldcg((const float4*)(Bp1 + (size_t)ktg * 128 + lane4));
                MMA_T4(acc0, ah, b0.x, b0.y);   // Ah*Bh
                MMA_T4(acc0, ah, b0.z, b0.w);   // Ah*Bl
                MMA_T4(acc0, al, b0.x, b0.y);   // Al*Bh
                MMA_T4(acc1, ah, b1.x, b1.y);
                MMA_T4(acc1, ah, b1.z, b1.w);
                MMA_T4(acc1, al, b1.x, b1.y);
            }
        }

        // scatter z fragments to smem: rows wm*16 + lane/4 (+8), cols gate*8 + (lane%3..)*2
        {
            int rr = wm * 16 + (lane >> 2);
            int c0i = (2 * wn) * 8 + (lane & 3) * 2;
            int c1i = (2 * wn + 1) * 8 + (lane & 3) * 2;
            zs[rr][c0i]     = acc0[0];
            zs[rr][c0i + 1] = acc0[1];
            zs[rr + 8][c0i]     = acc0[2];
            zs[rr + 8][c0i + 1] = acc0[3];
            zs[rr][c1i]     = acc1[0];
            zs[rr][c1i + 1] = acc1[1];
            zs[rr + 8][c1i]     = acc1[2];
            zs[rr + 8][c1i + 1] = acc1[3];
        }
        __syncthreads();

        // gating (c in registers); write packed h for next step (+ hseq/hlast)
        {
            int u = u0 + j0;
            float zi = zs[row0][j0]      + zx0[0];
            float zf = zs[row0][8 + j0]  + zx0[1];
            float zg = zs[row0][16 + j0] + zx0[2];
            float zo = zs[row0][24 + j0] + zx0[3];
            float ig = 1.f / (1.f + __expf(-zi));
            float fg = 1.f / (1.f + __expf(-zf));
            float og = 1.f / (1.f + __expf(-zo));
            c0 = fmaf(fg, c0, ig * zg);
            float hn = og * c0;
            float hi = cvt_tf32(hn);
            AhOut[pw0] = hi;
            AlOut[pw0] = cvt_tf32(hn - hi);
            if (hseq) hseq[(size_t)row0 * (TT * UU) + (size_t)t * UU + u] = hn;
            if (hlast && t == TT - 1) hlast[row0 * UU + u] = hn;
        }
        {
            int u = u0 + j0;
            float zi = zs[row1][j0]      + zx1[0];
            float zf = zs[row1][8 + j0]  + zx1[1];
            float zg = zs[row1][16 + j0] + zx1[2];
            float zo = zs[row1][24 + j0] + zx1[3];
            float ig = 1.f / (1.f + __expf(-zi));
            float fg = 1.f / (1.f + __expf(-zf));
            float og = 1.f / (1.f + __expf(-zo));
            c1 = fmaf(fg, c1, ig * zg);
            float hn = og * c1;
            float hi = cvt_tf32(hn);
            AhOut[pw1] = hi;
            AlOut[pw1] = cvt_tf32(hn - hi);
            if (hseq) hseq[(size_t)row1 * (TT * UU) + (size_t)t * UU + u] = hn;
            if (hlast && t == TT - 1) hlast[row1 * UU + u] = hn;
        }

        if (t != TT - 1)
            grid_barrier_step((unsigned)(t + 1));
    }
}

// ===========================================================================
// LayerNorm + tanh
// ===========================================================================
__global__ __launch_bounds__(256, 4)
void ln_tanh_kernel(const float* __restrict__ in, float* __restrict__ out,
                    const float* __restrict__ gamma, const float* __restrict__ beta)
{
    const int row = blockIdx.x;
    const float* xr = in + (size_t)row * UU;
    float* yr = out + (size_t)row * UU;
    const int tid = threadIdx.x;

    float v[4];
    float s = 0.f, sq = 0.f;
    #pragma unroll
    for (int q = 0; q < 4; q++) {
        v[q] = xr[tid + q * 256];
        s += v[q];
        sq = fmaf(v[q], v[q], sq);
    }
    __shared__ float sm1[8], sm2[8];
    #pragma unroll
    for (int o = 16; o > 0; o >>= 1) {
        s  += __shfl_xor_sync(0xffffffffu, s, o);
        sq += __shfl_xor_sync(0xffffffffu, sq, o);
    }
    if ((tid & 31) == 0) { sm1[tid >> 5] = s; sm2[tid >> 5] = sq; }
    __syncthreads();
    __shared__ float s_mu, s_inv;
    if (tid == 0) {
        float ts = 0.f, tq = 0.f;
        #pragma unroll
        for (int w = 0; w < 8; w++) { ts += sm1[w]; tq += sm2[w]; }
        float mu = ts * (1.f / UU);
        float var = tq * (1.f / UU) - mu * mu;
        s_mu = mu;
        s_inv = rsqrtf(var + LN_EPS);
    }
    __syncthreads();
    float mu = s_mu, inv = s_inv;
    #pragma unroll
    for (int q = 0; q < 4; q++) {
        int idx = tid + q * 256;
        float y = (v[q] - mu) * inv * gamma[idx] + beta[idx];
        yr[idx] = tanhf(y);
    }
}

// ===========================================================================
// Per-layer init: zero packed h0 (ping), reset barrier counter + epoch
// ===========================================================================
__global__ void init_kernel(float* __restrict__ hH, float* __restrict__ hL)
{
    int i = blockIdx.x * blockDim.x + threadIdx.x;
    if (i == 0) { g_barcnt[0] = 0u; g_epoch[0] = 0u; }
    if (i < 128 * 4 * 32 * 4) { hH[i] = 0.f; hL[i] = 0.f; }
}

// ===========================================================================
// Launch: 12 graph nodes
// ===========================================================================
extern "C" void kernel_launch(void* const* d_in, const int* in_sizes, int n_in,
                              void* d_out, int out_size)
{
    const float* x      = (const float*)d_in[0];
    const float* W1     = (const float*)d_in[1];
    const float* R1     = (const float*)d_in[2];
    const float* b1     = (const float*)d_in[3];
    const float* gamma1 = (const float*)d_in[4];
    const float* beta1  = (const float*)d_in[5];
    const float* W2     = (const float*)d_in[6];
    const float* R2     = (const float*)d_in[7];
    const float* b2     = (const float*)d_in[8];
    const float* gamma2 = (const float*)d_in[9];
    const float* beta2  = (const float*)d_in[10];
    float* out = (float*)d_out;

    float *zx, *hseq, *wt, *rp, *hpH0, *hpL0, *hpH1, *hpL1, *hlast;
    cudaGetSymbolAddress((void**)&zx,    g_zx);
    cudaGetSymbolAddress((void**)&hseq,  g_hseq);
    cudaGetSymbolAddress((void**)&wt,    g_wt);
    cudaGetSymbolAddress((void**)&rp,    g_rp);
    cudaGetSymbolAddress((void**)&hlast, g_hlast);
    { void* p; cudaGetSymbolAddress(&p, g_hp_hi); hpH0 = (float*)p; hpH1 = hpH0 + 128 * 4 * 32 * 4; }
    { void* p; cudaGetSymbolAddress(&p, g_hp_lo); hpL0 = (float*)p; hpL1 = hpL0 + 128 * 4 * 32 * 4; }

    cudaFuncSetAttribute(gemm_tf32_kernel,
                         cudaFuncAttributeMaxDynamicSharedMemorySize, GEMM_SMEM_BYTES);
    cudaFuncSetAttribute(lstm_mma_kernel,
                         cudaFuncAttributeMaxDynamicSharedMemorySize, 65536);

    const int M = BB * TT;                       // 32768
    const dim3 ggrid(G4 / 128, M / 128);         // (32, 256)
    const int initg = (128 * 4 * 32 * 4 + 255) / 256;

    // ---- Layer 1 ----
    transpose_kernel<<<dim3(G4 / 32, DD / 32), dim3(32, 8)>>>(W1, wt, DD, G4);
    gemm_tf32_kernel<<<ggrid, 256, GEMM_SMEM_BYTES>>>(x, wt, b1, zx, M, G4, DD);
    pack_r_kernel<<<8192, 256>>>(R1, rp);
    init_kernel<<<initg, 256>>>(hpH0, hpL0);
    lstm_mma_kernel<<<128, 256, 65536>>>(zx, rp, hpH0, hpL0, hpH1, hpL1, hseq, (float*)nullptr);
    ln_tanh_kernel<<<M, 256>>>(hseq, hseq, gamma1, beta1);

    // ---- Layer 2 ----
    transpose_kernel<<<dim3(G4 / 32, UU / 32), dim3(32, 8)>>>(W2, wt, UU, G4);
    gemm_tf32_kernel<<<ggrid, 256, GEMM_SMEM_BYTES>>>(hseq, wt, b2, zx, M, G4, UU);
    pack_r_kernel<<<8192, 256>>>(R2, rp);
    init_kernel<<<initg, 256>>>(hpH0, hpL0);
    lstm_mma_kernel<<<128, 256, 65536>>>(zx, rp, hpH0, hpL0, hpH1, hpL1, (float*)nullptr, hlast);
    ln_tanh_kernel<<<BB, 256>>>(hlast, out, gamma2, beta2);
}

// round 7
// speedup vs baseline: 4.3835x; 1.6450x over previous
#include <cuda_runtime.h>
#include <math.h>
#include <stdint.h>

// Problem constants
#define BB 64
#define TT 512
#define DD 512
#define UU 1024
#define G4 4096          // 4*UU
#define LN_EPS 1e-3f

// ---------------------------------------------------------------------------
// Scratch (device globals — no allocation allowed)
// ---------------------------------------------------------------------------
__device__ float g_zx[(size_t)BB * TT * G4];     // 512 MiB, reused by both layers
__device__ float g_hseq[(size_t)BB * TT * UU];   // 128 MiB
__device__ float g_wt[(size_t)G4 * UU];          // 16 MiB, W^T scratch (reused)
// packed R (tf32-hi, B-frag pair layout): [block 128][kt 128][pair 2][lane 32][4]
__device__ float g_rp2[(size_t)128 * 128 * 2 * 32 * 4];   // 16 MiB
// packed h hi (A-frag layout): [128 ktiles][4 mtiles][32 lanes][4 slots], ping/pong
__device__ float g_hp_hi[2][128 * 4 * 32 * 4];   // 256KB each
__device__ float g_hlast[BB * UU];
__device__ __align__(128) unsigned g_barcnt[32]; // arrival counter (own line)
__device__ __align__(128) unsigned g_epoch[32];  // epoch flag (own line)

// ---------------------------------------------------------------------------
// Helpers
// ---------------------------------------------------------------------------
__device__ __forceinline__ float cvt_tf32(float a) {
    float r;
    asm("cvt.rna.tf32.f32 %0, %1;" : "=f"(r) : "f"(a));
    return r;
}

#define MMA_TF32(d, a, b0v, b1v) \
    asm volatile("mma.sync.aligned.m16n8k8.row.col.f32.tf32.tf32.f32 " \
        "{%0,%1,%2,%3}, {%4,%5,%6,%7}, {%8,%9}, {%0,%1,%2,%3};" \
        : "+f"((d)[0]), "+f"((d)[1]), "+f"((d)[2]), "+f"((d)[3]) \
        : "r"((a)[0]), "r"((a)[1]), "r"((a)[2]), "r"((a)[3]), \
          "r"(b0v), "r"(b1v))

#define MMA_T4(d, av, b0v, b1v) \
    asm volatile("mma.sync.aligned.m16n8k8.row.col.f32.tf32.tf32.f32 " \
        "{%0,%1,%2,%3}, {%4,%5,%6,%7}, {%8,%9}, {%0,%1,%2,%3};" \
        : "+f"((d)[0]), "+f"((d)[1]), "+f"((d)[2]), "+f"((d)[3]) \
        : "r"(__float_as_uint((av).x)), "r"(__float_as_uint((av).y)), \
          "r"(__float_as_uint((av).z)), "r"(__float_as_uint((av).w)), \
          "r"(__float_as_uint(b0v)), "r"(__float_as_uint(b1v)))

// ===========================================================================
// Transpose: out[N][K] = in[K][N]
// ===========================================================================
__global__ __launch_bounds__(256)
void transpose_kernel(const float* __restrict__ in, float* __restrict__ out,
                      int K, int N)
{
    __shared__ float t[32][33];
    int bx = blockIdx.x * 32;   // N
    int by = blockIdx.y * 32;   // K
    int x = threadIdx.x, y = threadIdx.y;
    #pragma unroll
    for (int i = 0; i < 32; i += 8)
        t[y + i][x] = in[(size_t)(by + y + i) * N + bx + x];
    __syncthreads();
    #pragma unroll
    for (int i = 0; i < 32; i += 8)
        out[(size_t)(bx + y + i) * K + by + x] = t[x][y + i];
}

// ===========================================================================
// Pack R (tf32-hi) into per-block smem-ready B-frag pair layout:
//   Rp2[((b*128 + kt)*2 + p)*32 + lane] = float4{ g=2p:b0, g=2p:b1,
//                                                 g=2p+1:b0, g=2p+1:b1 }
//   b0 = R[kt*8 + lane%4   ][g*1024 + b*8 + lane/4]
//   b1 = R[kt*8 + 4 + lane%4][ same col ]
// ===========================================================================
__global__ __launch_bounds__(256)
void pack_r2_kernel(const float* __restrict__ R, float* __restrict__ Rp)
{
    int i = blockIdx.x * blockDim.x + threadIdx.x;   // float4 index
    int lane = i & 31;
    int p    = (i >> 5) & 1;
    int kt   = (i >> 6) & 127;
    int b    = i >> 13;
    int r0 = kt * 8 + (lane & 3);
    int j  = lane >> 2;
    int c0 = (2 * p) * UU + b * 8 + j;
    int c1 = (2 * p + 1) * UU + b * 8 + j;
    float4 o;
    o.x = cvt_tf32(__ldg(&R[(size_t)r0 * G4 + c0]));
    o.y = cvt_tf32(__ldg(&R[(size_t)(r0 + 4) * G4 + c0]));
    o.z = cvt_tf32(__ldg(&R[(size_t)r0 * G4 + c1]));
    o.w = cvt_tf32(__ldg(&R[(size_t)(r0 + 4) * G4 + c1]));
    *(float4*)&Rp[(size_t)i * 4] = o;
}

// ===========================================================================
// 3xTF32 mma.sync GEMM (unchanged):  C = A @ W + b, Bt = W^T
// ===========================================================================
#define TSZ (128 * 36)
#define GEMM_SMEM_BYTES (4 * TSZ * 4)

__global__ __launch_bounds__(256, 2)
void gemm_tf32_kernel(const float* __restrict__ A, const float* __restrict__ Bt,
                      const float* __restrict__ bias, float* __restrict__ C,
                      int M, int N, int K)
{
    extern __shared__ float sm[];
    float* As_hi = sm;
    float* As_lo = sm + TSZ;
    float* Bs_hi = sm + 2 * TSZ;
    float* Bs_lo = sm + 3 * TSZ;

    const int tid  = threadIdx.x;
    const int m0   = blockIdx.y * 128;
    const int n0   = blockIdx.x * 128;
    const int lane = tid & 31, wid = tid >> 5;
    const int wm   = (wid & 3) * 32;
    const int wn   = (wid >> 2) * 64;
    const int g    = lane >> 2, ii = lane & 3;

    float acc[2][8][4];
    #pragma unroll
    for (int mi = 0; mi < 2; mi++)
        #pragma unroll
        for (int ni = 0; ni < 8; ni++)
            #pragma unroll
            for (int q = 0; q < 4; q++) acc[mi][ni][q] = 0.f;

    for (int k0 = 0; k0 < K; k0 += 32) {
        __syncthreads();
        #pragma unroll
        for (int p = 0; p < 4; p++) {
            int idx = p * 256 + tid;
            int r = idx >> 3, c = (idx & 7) * 4;
            {
                float4 v = __ldg((const float4*)&A[(size_t)(m0 + r) * K + k0 + c]);
                float4 hi, lo;
                hi.x = cvt_tf32(v.x); lo.x = cvt_tf32(v.x - hi.x);
                hi.y = cvt_tf32(v.y); lo.y = cvt_tf32(v.y - hi.y);
                hi.z = cvt_tf32(v.z); lo.z = cvt_tf32(v.z - hi.z);
                hi.w = cvt_tf32(v.w); lo.w = cvt_tf32(v.w - hi.w);
                *(float4*)&As_hi[r * 36 + c] = hi;
                *(float4*)&As_lo[r * 36 + c] = lo;
            }
            {
                float4 v = __ldg((const float4*)&Bt[(size_t)(n0 + r) * K + k0 + c]);
                float4 hi, lo;
                hi.x = cvt_tf32(v.x); lo.x = cvt_tf32(v.x - hi.x);
                hi.y = cvt_tf32(v.y); lo.y = cvt_tf32(v.y - hi.y);
                hi.z = cvt_tf32(v.z); lo.z = cvt_tf32(v.z - hi.z);
                hi.w = cvt_tf32(v.w); lo.w = cvt_tf32(v.w - hi.w);
                *(float4*)&Bs_hi[r * 36 + c] = hi;
                *(float4*)&Bs_lo[r * 36 + c] = lo;
            }
        }
        __syncthreads();

        #pragma unroll
        for (int ks = 0; ks < 4; ks++) {
            const int kb = ks * 8;
            uint32_t ah[2][4], al[2][4];
            #pragma unroll
            for (int mi = 0; mi < 2; mi++) {
                int r0 = (wm + mi * 16 + g) * 36 + kb;
                int r8 = (wm + mi * 16 + g + 8) * 36 + kb;
                ah[mi][0] = __float_as_uint(As_hi[r0 + ii]);
                ah[mi][1] = __float_as_uint(As_hi[r8 + ii]);
                ah[mi][2] = __float_as_uint(As_hi[r0 + ii + 4]);
                ah[mi][3] = __float_as_uint(As_hi[r8 + ii + 4]);
                al[mi][0] = __float_as_uint(As_lo[r0 + ii]);
                al[mi][1] = __float_as_uint(As_lo[r8 + ii]);
                al[mi][2] = __float_as_uint(As_lo[r0 + ii + 4]);
                al[mi][3] = __float_as_uint(As_lo[r8 + ii + 4]);
            }
            #pragma unroll
            for (int ni = 0; ni < 8; ni++) {
                int nb = (wn + ni * 8 + g) * 36 + kb;
                uint32_t bh0 = __float_as_uint(Bs_hi[nb + ii]);
                uint32_t bh1 = __float_as_uint(Bs_hi[nb + ii + 4]);
                uint32_t bl0 = __float_as_uint(Bs_lo[nb + ii]);
                uint32_t bl1 = __float_as_uint(Bs_lo[nb + ii + 4]);
                #pragma unroll
                for (int mi = 0; mi < 2; mi++) {
                    MMA_TF32(acc[mi][ni], ah[mi], bh0, bh1);
                    MMA_TF32(acc[mi][ni], ah[mi], bl0, bl1);
                    MMA_TF32(acc[mi][ni], al[mi], bh0, bh1);
                }
            }
        }
    }

    #pragma unroll
    for (int mi = 0; mi < 2; mi++) {
        int r0 = m0 + wm + mi * 16 + g;
        #pragma unroll
        for (int ni = 0; ni < 8; ni++) {
            int cc = n0 + wn + ni * 8 + ii * 2;
            float b0v = __ldg(&bias[cc]);
            float b1v = __ldg(&bias[cc + 1]);
            float2 o0 = make_float2(acc[mi][ni][0] + b0v, acc[mi][ni][1] + b1v);
            float2 o1 = make_float2(acc[mi][ni][2] + b0v, acc[mi][ni][3] + b1v);
            *(float2*)&C[(size_t)r0 * N + cc] = o0;
            *(float2*)&C[(size_t)(r0 + 8) * N + cc] = o1;
        }
    }
}

// ===========================================================================
// Fast grid barrier
// ===========================================================================
__device__ __forceinline__ void grid_barrier_step(unsigned t1)
{
    __syncthreads();
    if (threadIdx.x == 0) {
        unsigned old;
        asm volatile("atom.release.gpu.global.add.u32 %0, [%1], %2;"
                     : "=r"(old) : "l"(&g_barcnt[0]), "r"(1u) : "memory");
        if (old + 1u == 128u * t1) {
            asm volatile("st.release.gpu.global.u32 [%0], %1;"
                         :: "l"(&g_epoch[0]), "r"(t1) : "memory");
        } else {
            unsigned e;
            do {
                __nanosleep(64);
                asm volatile("ld.acquire.gpu.global.u32 %0, [%1];"
                             : "=r"(e) : "l"(&g_epoch[0]) : "memory");
            } while (e < t1);
        }
    }
    __syncthreads();
}

// ===========================================================================
// Persistent LSTM layer, pure-TF32 recurrence.
// 128 blocks x 256 threads (8 warps: wm=wid&3, wn=wid>>2).
// R (tf32-hi) lives entirely in SMEM (128 KB, loaded once).
// h (tf32-hi) read directly from L2 per ktile (1 LDG.128/warp/kt).
// Per kt per warp: 1 LDG.128 + 1 LDS.128 + 2 MMA.
// ===========================================================================
__global__ __launch_bounds__(256, 1)
void lstm_mma_kernel(const float* __restrict__ zx,     // [B*TT][G4], row=b*TT+t
                     const float* __restrict__ Rp,     // packed tf32-hi
                     float* __restrict__ hpH0, float* __restrict__ hpH1,
                     float* __restrict__ hseq,         // [B][TT][UU] or null
                     float* __restrict__ hlast)        // [B][UU] or null
{
    extern __shared__ float Rs[];      // 32768 floats = 128 KB
    __shared__ float zs[64][33];

    const int tid  = threadIdx.x;
    const int b    = blockIdx.x;       // 0..127
    const int u0   = b * 8;
    const int lane = tid & 31, wid = tid >> 5;
    const int wm   = wid & 3;          // m-tile 0..3
    const int wn   = wid >> 2;         // gate pair 0..1
    const int lane4 = lane * 4;

    // load this block's packed R into smem (once)
    {
        const float4* src = (const float4*)(Rp + (size_t)b * 32768);
        float4* dst = (float4*)Rs;
        #pragma unroll
        for (int q = 0; q < 32; q++)
            dst[q * 256 + tid] = __ldg(&src[q * 256 + tid]);
    }
    __syncthreads();

    // gating ownership
    const int row0 = tid >> 3, j0 = tid & 7;
    const int row1 = row0 + 32;
    float c0 = 0.f, c1 = 0.f;

    // packed-write index for gating (A-frag layout), ktile == b
    auto pidx = [&](int row) {
        int mt = row >> 4, mm = row & 15;
        int lw = (mm & 7) * 4 + (j0 & 3);
        int slot = ((mm >> 3) & 1) + ((j0 >> 2) << 1);
        return (b * 4 + mt) * 128 + lw * 4 + slot;
    };
    const int pw0 = pidx(row0);
    const int pw1 = pidx(row1);

    for (int t = 0; t < TT; t++) {
        const float* Ain  = (t & 1) ? hpH1 : hpH0;
        float*       Aout = (t & 1) ? hpH0 : hpH1;

        // zx prefetch (gate inputs, independent of h)
        float zx0[4], zx1[4];
        {
            const float* z0 = zx + (size_t)row0 * (TT * G4) + (size_t)t * G4 + u0 + j0;
            const float* z1 = zx + (size_t)row1 * (TT * G4) + (size_t)t * G4 + u0 + j0;
            #pragma unroll
            for (int g = 0; g < 4; g++) { zx0[g] = __ldcs(z0 + g * UU); zx1[g] = __ldcs(z1 + g * UU); }
        }

        float acc0[4] = {0.f, 0.f, 0.f, 0.f};
        float acc1[4] = {0.f, 0.f, 0.f, 0.f};

        #pragma unroll 8
        for (int kt = 0; kt < 128; kt++) {
            float4 a4 = __ldcg((const float4*)&Ain[(kt * 4 + wm) * 128 + lane4]);
            float4 r4 = *(const float4*)&Rs[(kt * 2 + wn) * 128 + lane4];
            MMA_T4(acc0, a4, r4.x, r4.y);   // gate 2*wn
            MMA_T4(acc1, a4, r4.z, r4.w);   // gate 2*wn+1
        }

        // scatter z fragments to smem
        {
            int rr  = wm * 16 + (lane >> 2);
            int c0i = (2 * wn) * 8 + (lane & 3) * 2;
            int c1i = (2 * wn + 1) * 8 + (lane & 3) * 2;
            zs[rr][c0i]         = acc0[0];
            zs[rr][c0i + 1]     = acc0[1];
            zs[rr + 8][c0i]     = acc0[2];
            zs[rr + 8][c0i + 1] = acc0[3];
            zs[rr][c1i]         = acc1[0];
            zs[rr][c1i + 1]     = acc1[1];
            zs[rr + 8][c1i]     = acc1[2];
            zs[rr + 8][c1i + 1] = acc1[3];
        }
        __syncthreads();

        // gating (c in registers); write tf32-hi packed h + exact hseq/hlast
        {
            int u = u0 + j0;
            float zi = zs[row0][j0]      + zx0[0];
            float zf = zs[row0][8 + j0]  + zx0[1];
            float zg = zs[row0][16 + j0] + zx0[2];
            float zo = zs[row0][24 + j0] + zx0[3];
            float ig = 1.f / (1.f + __expf(-zi));
            float fg = 1.f / (1.f + __expf(-zf));
            float og = 1.f / (1.f + __expf(-zo));
            c0 = fmaf(fg, c0, ig * zg);
            float hn = og * c0;
            Aout[pw0] = cvt_tf32(hn);
            if (hseq) hseq[(size_t)row0 * (TT * UU) + (size_t)t * UU + u] = hn;
            if (hlast && t == TT - 1) hlast[row0 * UU + u] = hn;
        }
        {
            int u = u0 + j0;
            float zi = zs[row1][j0]      + zx1[0];
            float zf = zs[row1][8 + j0]  + zx1[1];
            float zg = zs[row1][16 + j0] + zx1[2];
            float zo = zs[row1][24 + j0] + zx1[3];
            float ig = 1.f / (1.f + __expf(-zi));
            float fg = 1.f / (1.f + __expf(-zf));
            float og = 1.f / (1.f + __expf(-zo));
            c1 = fmaf(fg, c1, ig * zg);
            float hn = og * c1;
            Aout[pw1] = cvt_tf32(hn);
            if (hseq) hseq[(size_t)row1 * (TT * UU) + (size_t)t * UU + u] = hn;
            if (hlast && t == TT - 1) hlast[row1 * UU + u] = hn;
        }

        if (t != TT - 1)
            grid_barrier_step((unsigned)(t + 1));
    }
}

// ===========================================================================
// LayerNorm + tanh
// ===========================================================================
__global__ __launch_bounds__(256, 4)
void ln_tanh_kernel(const float* __restrict__ in, float* __restrict__ out,
                    const float* __restrict__ gamma, const float* __restrict__ beta)
{
    const int row = blockIdx.x;
    const float* xr = in + (size_t)row * UU;
    float* yr = out + (size_t)row * UU;
    const int tid = threadIdx.x;

    float v[4];
    float s = 0.f, sq = 0.f;
    #pragma unroll
    for (int q = 0; q < 4; q++) {
        v[q] = xr[tid + q * 256];
        s += v[q];
        sq = fmaf(v[q], v[q], sq);
    }
    __shared__ float sm1[8], sm2[8];
    #pragma unroll
    for (int o = 16; o > 0; o >>= 1) {
        s  += __shfl_xor_sync(0xffffffffu, s, o);
        sq += __shfl_xor_sync(0xffffffffu, sq, o);
    }
    if ((tid & 31) == 0) { sm1[tid >> 5] = s; sm2[tid >> 5] = sq; }
    __syncthreads();
    __shared__ float s_mu, s_inv;
    if (tid == 0) {
        float ts = 0.f, tq = 0.f;
        #pragma unroll
        for (int w = 0; w < 8; w++) { ts += sm1[w]; tq += sm2[w]; }
        float mu = ts * (1.f / UU);
        float var = tq * (1.f / UU) - mu * mu;
        s_mu = mu;
        s_inv = rsqrtf(var + LN_EPS);
    }
    __syncthreads();
    float mu = s_mu, inv = s_inv;
    #pragma unroll
    for (int q = 0; q < 4; q++) {
        int idx = tid + q * 256;
        float y = (v[q] - mu) * inv * gamma[idx] + beta[idx];
        yr[idx] = tanhf(y);
    }
}

// ===========================================================================
// Per-layer init: zero packed h0 (ping), reset barrier counter + epoch
// ===========================================================================
__global__ void init_kernel(float* __restrict__ hH)
{
    int i = blockIdx.x * blockDim.x + threadIdx.x;
    if (i == 0) { g_barcnt[0] = 0u; g_epoch[0] = 0u; }
    if (i < 128 * 4 * 32 * 4) hH[i] = 0.f;
}

// ===========================================================================
// Launch: 12 graph nodes
// ===========================================================================
extern "C" void kernel_launch(void* const* d_in, const int* in_sizes, int n_in,
                              void* d_out, int out_size)
{
    const float* x      = (const float*)d_in[0];
    const float* W1     = (const float*)d_in[1];
    const float* R1     = (const float*)d_in[2];
    const float* b1     = (const float*)d_in[3];
    const float* gamma1 = (const float*)d_in[4];
    const float* beta1  = (const float*)d_in[5];
    const float* W2     = (const float*)d_in[6];
    const float* R2     = (const float*)d_in[7];
    const float* b2     = (const float*)d_in[8];
    const float* gamma2 = (const float*)d_in[9];
    const float* beta2  = (const float*)d_in[10];
    float* out = (float*)d_out;

    float *zx, *hseq, *wt, *rp, *hpH0, *hpH1, *hlast;
    cudaGetSymbolAddress((void**)&zx,    g_zx);
    cudaGetSymbolAddress((void**)&hseq,  g_hseq);
    cudaGetSymbolAddress((void**)&wt,    g_wt);
    cudaGetSymbolAddress((void**)&rp,    g_rp2);
    cudaGetSymbolAddress((void**)&hlast, g_hlast);
    { void* p; cudaGetSymbolAddress(&p, g_hp_hi); hpH0 = (float*)p; hpH1 = hpH0 + 128 * 4 * 32 * 4; }

    cudaFuncSetAttribute(gemm_tf32_kernel,
                         cudaFuncAttributeMaxDynamicSharedMemorySize, GEMM_SMEM_BYTES);
    cudaFuncSetAttribute(lstm_mma_kernel,
                         cudaFuncAttributeMaxDynamicSharedMemorySize, 131072);

    const int M = BB * TT;                       // 32768
    const dim3 ggrid(G4 / 128, M / 128);         // (32, 256)
    const int initg = (128 * 4 * 32 * 4 + 255) / 256;
    const int packg = (128 * 128 * 2 * 32) / 256;

    // ---- Layer 1 ----
    transpose_kernel<<<dim3(G4 / 32, DD / 32), dim3(32, 8)>>>(W1, wt, DD, G4);
    gemm_tf32_kernel<<<ggrid, 256, GEMM_SMEM_BYTES>>>(x, wt, b1, zx, M, G4, DD);
    pack_r2_kernel<<<packg, 256>>>(R1, rp);
    init_kernel<<<initg, 256>>>(hpH0);
    lstm_mma_kernel<<<128, 256, 131072>>>(zx, rp, hpH0, hpH1, hseq, (float*)nullptr);
    ln_tanh_kernel<<<M, 256>>>(hseq, hseq, gamma1, beta1);

    // ---- Layer 2 ----
    transpose_kernel<<<dim3(G4 / 32, UU / 32), dim3(32, 8)>>>(W2, wt, UU, G4);
    gemm_tf32_kernel<<<ggrid, 256, GEMM_SMEM_BYTES>>>(hseq, wt, b2, zx, M, G4, UU);
    pack_r2_kernel<<<packg, 256>>>(R2, rp);
    init_kernel<<<initg, 256>>>(hpH0);
    lstm_mma_kernel<<<128, 256, 131072>>>(zx, rp, hpH0, hpH1, (float*)nullptr, hlast);
    ln_tanh_kernel<<<BB, 256>>>(hlast, out, gamma2, beta2);
}

// round 10
// speedup vs baseline: 4.6974x; 1.0716x over previous
#include <cuda_runtime.h>
#include <math.h>
#include <stdint.h>

// Problem constants
#define BB 64
#define TT 512
#define DD 512
#define UU 1024
#define G4 4096          // 4*UU
#define LN_EPS 1e-3f

// ---------------------------------------------------------------------------
// Scratch (device globals — no allocation allowed)
// ---------------------------------------------------------------------------
__device__ float g_zx[(size_t)BB * TT * G4];     // 512 MiB, reused by both layers
__device__ float g_hseq[(size_t)BB * TT * UU];   // 128 MiB
// packed R (tf32-hi, B-frag pair layout): [block 128][kt 128][pair 2][lane 32][4]
__device__ float g_rp2[(size_t)128 * 128 * 2 * 32 * 4];   // 16 MiB
// packed h hi (A-frag layout): [128 ktiles][4 mtiles][32 lanes][4 slots], ping/pong
__device__ float g_hp_hi[2][128 * 4 * 32 * 4];   // 256KB each
__device__ float g_hlast[BB * UU];
__device__ __align__(128) unsigned g_barcnt[32]; // arrival counter (own line)
__device__ __align__(128) unsigned g_epoch[32];  // epoch flag (own line)

// ---------------------------------------------------------------------------
// Helpers
// ---------------------------------------------------------------------------
__device__ __forceinline__ float cvt_tf32(float a) {
    float r;
    asm("cvt.rna.tf32.f32 %0, %1;" : "=f"(r) : "f"(a));
    return r;
}

__device__ __forceinline__ void cp16(void* s, const void* g) {
    uint32_t sa = (uint32_t)__cvta_generic_to_shared(s);
    asm volatile("cp.async.cg.shared.global [%0], [%1], 16;" :: "r"(sa), "l"(g));
}
#define CP_COMMIT()  asm volatile("cp.async.commit_group;" ::: "memory")
#define CP_WAIT(n)   asm volatile("cp.async.wait_group %0;" :: "n"(n) : "memory")

#define MMA_TF32(d, a, b0v, b1v) \
    asm volatile("mma.sync.aligned.m16n8k8.row.col.f32.tf32.tf32.f32 " \
        "{%0,%1,%2,%3}, {%4,%5,%6,%7}, {%8,%9}, {%0,%1,%2,%3};" \
        : "+f"((d)[0]), "+f"((d)[1]), "+f"((d)[2]), "+f"((d)[3]) \
        : "r"((a)[0]), "r"((a)[1]), "r"((a)[2]), "r"((a)[3]), \
          "r"(b0v), "r"(b1v))

#define MMA_T4(d, av, b0v, b1v) \
    asm volatile("mma.sync.aligned.m16n8k8.row.col.f32.tf32.tf32.f32 " \
        "{%0,%1,%2,%3}, {%4,%5,%6,%7}, {%8,%9}, {%0,%1,%2,%3};" \
        : "+f"((d)[0]), "+f"((d)[1]), "+f"((d)[2]), "+f"((d)[3]) \
        : "r"(__float_as_uint((av).x)), "r"(__float_as_uint((av).y)), \
          "r"(__float_as_uint((av).z)), "r"(__float_as_uint((av).w)), \
          "r"(__float_as_uint(b0v)), "r"(__float_as_uint(b1v)))

// ===========================================================================
// Pack R (tf32-hi) into per-block smem-ready B-frag pair layout.
// ===========================================================================
__global__ __launch_bounds__(256)
void pack_r2_kernel(const float* __restrict__ R, float* __restrict__ Rp)
{
    int i = blockIdx.x * blockDim.x + threadIdx.x;   // float4 index
    int lane = i & 31;
    int p    = (i >> 5) & 1;
    int kt   = (i >> 6) & 127;
    int b    = i >> 13;
    int r0 = kt * 8 + (lane & 3);
    int j  = lane >> 2;
    int c0 = (2 * p) * UU + b * 8 + j;
    int c1 = (2 * p + 1) * UU + b * 8 + j;
    float4 o;
    o.x = cvt_tf32(__ldg(&R[(size_t)r0 * G4 + c0]));
    o.y = cvt_tf32(__ldg(&R[(size_t)(r0 + 4) * G4 + c0]));
    o.z = cvt_tf32(__ldg(&R[(size_t)r0 * G4 + c1]));
    o.w = cvt_tf32(__ldg(&R[(size_t)(r0 + 4) * G4 + c1]));
    *(float4*)&Rp[(size_t)i * 4] = o;
}

// ===========================================================================
// 3xTF32 GEMM with cp.async double-buffering and fused W transpose:
//   C[M,N] = A[M,K] @ W[K,N] + b      (W consumed directly, no pre-transpose)
// Block 128x128, BK=32, 256 threads (8 warps: 4m x 2n, warp tile 32x64).
// Raw f32 staged in smem; tf32 hi/lo computed at fragment-build time.
// B tile is 32 k-rows x 128 n-cols; B_LD=136 (136%32==8 -> warp bank index
// (ii*8+g)%32 all distinct -> conflict-free B-frag reads).
// ===========================================================================
#define GBK   32
#define A_LD  36                  // floats/row (bank (g*4+ii)%32 distinct)
#define B_LD  136                 // floats/row: 128 data + 8 pad
#define ASZ   (128 * A_LD)        // 4608 floats
#define BSZ   (GBK * B_LD)        // 4352 floats
#define GEMM_SMEM_BYTES (2 * (ASZ + BSZ) * 4)   // 71680 B

__global__ __launch_bounds__(256, 2)
void gemm_tf32_kernel(const float* __restrict__ A, const float* __restrict__ W,
                      const float* __restrict__ bias, float* __restrict__ C,
                      int M, int N, int K)
{
    extern __shared__ float sm[];
    float* Asm[2] = { sm, sm + ASZ };
    float* Bsm[2] = { sm + 2 * ASZ, sm + 2 * ASZ + BSZ };

    const int tid  = threadIdx.x;
    const int m0   = blockIdx.y * 128;
    const int n0   = blockIdx.x * 128;
    const int lane = tid & 31, wid = tid >> 5;
    const int wm   = (wid & 3) * 32;
    const int wn   = (wid >> 2) * 64;
    const int g    = lane >> 2, ii = lane & 3;

    // per-thread load coords
    const int a_r = tid >> 3, a_c = (tid & 7) * 4;     // + p*32 rows
    const int b_r = tid >> 5, b_c = (tid & 31) * 4;    // + p*8 rows

    float acc[2][8][4];
    #pragma unroll
    for (int mi = 0; mi < 2; mi++)
        #pragma unroll
        for (int ni = 0; ni < 8; ni++)
            #pragma unroll
            for (int q = 0; q < 4; q++) acc[mi][ni][q] = 0.f;

    const int nk = K >> 5;

    // prologue: chunk 0
    {
        #pragma unroll
        for (int p = 0; p < 4; p++)
            cp16(&Asm[0][(a_r + p * 32) * A_LD + a_c],
                 &A[(size_t)(m0 + a_r + p * 32) * K + a_c]);
        #pragma unroll
        for (int p = 0; p < 4; p++)
            cp16(&Bsm[0][(b_r + p * 8) * B_LD + b_c],
                 &W[(size_t)(b_r + p * 8) * N + n0 + b_c]);
        CP_COMMIT();
    }

    for (int ch = 0; ch < nk; ch++) {
        const int buf = ch & 1;
        if (ch + 1 < nk) {
            const int k0 = (ch + 1) << 5;
            #pragma unroll
            for (int p = 0; p < 4; p++)
                cp16(&Asm[buf ^ 1][(a_r + p * 32) * A_LD + a_c],
                     &A[(size_t)(m0 + a_r + p * 32) * K + k0 + a_c]);
            #pragma unroll
            for (int p = 0; p < 4; p++)
                cp16(&Bsm[buf ^ 1][(b_r + p * 8) * B_LD + b_c],
                     &W[(size_t)(k0 + b_r + p * 8) * N + n0 + b_c]);
            CP_COMMIT();
            CP_WAIT(1);
        } else {
            CP_WAIT(0);
        }
        __syncthreads();

        const float* Ab = Asm[buf];
        const float* Bb = Bsm[buf];
        #pragma unroll
        for (int ks = 0; ks < 4; ks++) {
            const int kb = ks * 8;
            uint32_t ah[2][4], al[2][4];
            #pragma unroll
            for (int mi = 0; mi < 2; mi++) {
                int r0 = (wm + mi * 16 + g) * A_LD + kb + ii;
                int r8 = r0 + 8 * A_LD;
                float v0 = Ab[r0],     v1 = Ab[r8];
                float v2 = Ab[r0 + 4], v3 = Ab[r8 + 4];
                float h0 = cvt_tf32(v0), h1 = cvt_tf32(v1);
                float h2 = cvt_tf32(v2), h3 = cvt_tf32(v3);
                ah[mi][0] = __float_as_uint(h0); al[mi][0] = __float_as_uint(cvt_tf32(v0 - h0));
                ah[mi][1] = __float_as_uint(h1); al[mi][1] = __float_as_uint(cvt_tf32(v1 - h1));
                ah[mi][2] = __float_as_uint(h2); al[mi][2] = __float_as_uint(cvt_tf32(v2 - h2));
                ah[mi][3] = __float_as_uint(h3); al[mi][3] = __float_as_uint(cvt_tf32(v3 - h3));
            }
            #pragma unroll
            for (int ni = 0; ni < 8; ni++) {
                int nb = wn + ni * 8 + g;
                float w0 = Bb[(kb + ii) * B_LD + nb];
                float w1 = Bb[(kb + ii + 4) * B_LD + nb];
                float bh0f = cvt_tf32(w0), bh1f = cvt_tf32(w1);
                uint32_t bh0 = __float_as_uint(bh0f);
                uint32_t bh1 = __float_as_uint(bh1f);
                uint32_t bl0 = __float_as_uint(cvt_tf32(w0 - bh0f));
                uint32_t bl1 = __float_as_uint(cvt_tf32(w1 - bh1f));
                #pragma unroll
                for (int mi = 0; mi < 2; mi++) {
                    MMA_TF32(acc[mi][ni], ah[mi], bh0, bh1);
                    MMA_TF32(acc[mi][ni], ah[mi], bl0, bl1);
                    MMA_TF32(acc[mi][ni], al[mi], bh0, bh1);
                }
            }
        }
        __syncthreads();
    }

    #pragma unroll
    for (int mi = 0; mi < 2; mi++) {
        int r0 = m0 + wm + mi * 16 + g;
        #pragma unroll
        for (int ni = 0; ni < 8; ni++) {
            int cc = n0 + wn + ni * 8 + ii * 2;
            float b0v = __ldg(&bias[cc]);
            float b1v = __ldg(&bias[cc + 1]);
            float2 o0 = make_float2(acc[mi][ni][0] + b0v, acc[mi][ni][1] + b1v);
            float2 o1 = make_float2(acc[mi][ni][2] + b0v, acc[mi][ni][3] + b1v);
            *(float2*)&C[(size_t)r0 * N + cc] = o0;
            *(float2*)&C[(size_t)(r0 + 8) * N + cc] = o1;
        }
    }
}

// ===========================================================================
// Fast grid barrier
// ===========================================================================
__device__ __forceinline__ void grid_barrier_step(unsigned t1)
{
    __syncthreads();
    if (threadIdx.x == 0) {
        unsigned old;
        asm volatile("atom.release.gpu.global.add.u32 %0, [%1], %2;"
                     : "=r"(old) : "l"(&g_barcnt[0]), "r"(1u) : "memory");
        if (old + 1u == 128u * t1) {
            asm volatile("st.release.gpu.global.u32 [%0], %1;"
                         :: "l"(&g_epoch[0]), "r"(t1) : "memory");
        } else {
            unsigned e;
            do {
                __nanosleep(32);
                asm volatile("ld.acquire.gpu.global.u32 %0, [%1];"
                             : "=r"(e) : "l"(&g_epoch[0]) : "memory");
            } while (e < t1);
        }
    }
    __syncthreads();
}

// ===========================================================================
// Persistent LSTM layer, pure-TF32 recurrence with cp.async h staging.
// 128 blocks x 256 threads (8 warps: wm=wid&3, wn=wid>>2).
// R (tf32-hi) in SMEM (128 KB, once). h staged per-step in 8 chunks of
// 32 KB via depth-2 cp.async.cg pipeline (L2-coherent across grid barrier).
// ===========================================================================
#define LSTM_SMEM_BYTES ((32768 + 2 * 8192) * 4)    // 196608

__global__ __launch_bounds__(256, 1)
void lstm_mma_kernel(const float* __restrict__ zx,     // [B*TT][G4], row=b*TT+t
                     const float* __restrict__ Rp,     // packed tf32-hi
                     float* __restrict__ hpH0, float* __restrict__ hpH1,
                     float* __restrict__ hseq,         // [B][TT][UU] or null
                     float* __restrict__ hlast)        // [B][UU] or null
{
    extern __shared__ float dsm[];
    float* Rs = dsm;                 // 32768 floats
    float* Hs = dsm + 32768;         // 2 x 8192 floats
    __shared__ float zs[64][33];

    const int tid  = threadIdx.x;
    const int b    = blockIdx.x;     // 0..127
    const int u0   = b * 8;
    const int lane = tid & 31, wid = tid >> 5;
    const int wm   = wid & 3;
    const int wn   = wid >> 2;
    const int lane4 = lane * 4;

    // load this block's packed R into smem (once)
    {
        const float4* src = (const float4*)(Rp + (size_t)b * 32768);
        float4* dst = (float4*)Rs;
        #pragma unroll
        for (int q = 0; q < 32; q++)
            dst[q * 256 + tid] = __ldg(&src[q * 256 + tid]);
    }
    __syncthreads();

    // gating ownership
    const int row0 = tid >> 3, j0 = tid & 7;
    const int row1 = row0 + 32;
    float c0 = 0.f, c1 = 0.f;

    auto pidx = [&](int row) {
        int mt = row >> 4, mm = row & 15;
        int lw = (mm & 7) * 4 + (j0 & 3);
        int slot = ((mm >> 3) & 1) + ((j0 >> 2) << 1);
        return (b * 4 + mt) * 128 + lw * 4 + slot;
    };
    const int pw0 = pidx(row0);
    const int pw1 = pidx(row1);

    for (int t = 0; t < TT; t++) {
        const float* Ain  = (t & 1) ? hpH1 : hpH0;
        float*       Aout = (t & 1) ? hpH0 : hpH1;

        // zx prefetch (gate inputs, independent of h)
        float zx0[4], zx1[4];
        {
            const float* z0 = zx + (size_t)row0 * (TT * G4) + (size_t)t * G4 + u0 + j0;
            const float* z1 = zx + (size_t)row1 * (TT * G4) + (size_t)t * G4 + u0 + j0;
            #pragma unroll
            for (int g = 0; g < 4; g++) { zx0[g] = __ldcs(z0 + g * UU); zx1[g] = __ldcs(z1 + g * UU); }
        }

        float acc0[4] = {0.f, 0.f, 0.f, 0.f};
        float acc1[4] = {0.f, 0.f, 0.f, 0.f};

        // prologue: stage chunk 0 (h ktiles 0..15)
        {
            const float4* src = (const float4*)Ain;
            #pragma unroll
            for (int p = 0; p < 8; p++)
                cp16(&Hs[(p * 256 + tid) * 4], &src[p * 256 + tid]);
            CP_COMMIT();
        }

        for (int ch = 0; ch < 8; ch++) {
            const int buf = ch & 1;
            if (ch < 7) {
                const float4* src = (const float4*)(Ain + (ch + 1) * 8192);
                float* dst = Hs + (buf ^ 1) * 8192;
                #pragma unroll
                for (int p = 0; p < 8; p++)
                    cp16(&dst[(p * 256 + tid) * 4], &src[p * 256 + tid]);
                CP_COMMIT();
                CP_WAIT(1);
            } else {
                CP_WAIT(0);
            }
            __syncthreads();

            const float* Hb = Hs + buf * 8192;
            #pragma unroll
            for (int kt = 0; kt < 16; kt++) {
                float4 a4 = *(const float4*)&Hb[(kt * 4 + wm) * 128 + lane4];
                float4 r4 = *(const float4*)&Rs[(((ch * 16 + kt) * 2) + wn) * 128 + lane4];
                MMA_T4(acc0, a4, r4.x, r4.y);   // gate 2*wn
                MMA_T4(acc1, a4, r4.z, r4.w);   // gate 2*wn+1
            }
            __syncthreads();
        }

        // scatter z fragments to smem
        {
            int rr  = wm * 16 + (lane >> 2);
            int c0i = (2 * wn) * 8 + (lane & 3) * 2;
            int c1i = (2 * wn + 1) * 8 + (lane & 3) * 2;
            zs[rr][c0i]         = acc0[0];
            zs[rr][c0i + 1]     = acc0[1];
            zs[rr + 8][c0i]     = acc0[2];
            zs[rr + 8][c0i + 1] = acc0[3];
            zs[rr][c1i]         = acc1[0];
            zs[rr][c1i + 1]     = acc1[1];
            zs[rr + 8][c1i]     = acc1[2];
            zs[rr + 8][c1i + 1] = acc1[3];
        }
        __syncthreads();

        // gating (c in registers); write tf32-hi packed h + exact hseq/hlast
        {
            int u = u0 + j0;
            float zi = zs[row0][j0]      + zx0[0];
            float zf = zs[row0][8 + j0]  + zx0[1];
            float zg = zs[row0][16 + j0] + zx0[2];
            float zo = zs[row0][24 + j0] + zx0[3];
            float ig = 1.f / (1.f + __expf(-zi));
            float fg = 1.f / (1.f + __expf(-zf));
            float og = 1.f / (1.f + __expf(-zo));
            c0 = fmaf(fg, c0, ig * zg);
            float hn = og * c0;
            Aout[pw0] = cvt_tf32(hn);
            if (hseq) hseq[(size_t)row0 * (TT * UU) + (size_t)t * UU + u] = hn;
            if (hlast && t == TT - 1) hlast[row0 * UU + u] = hn;
        }
        {
            int u = u0 + j0;
            float zi = zs[row1][j0]      + zx1[0];
            float zf = zs[row1][8 + j0]  + zx1[1];
            float zg = zs[row1][16 + j0] + zx1[2];
            float zo = zs[row1][24 + j0] + zx1[3];
            float ig = 1.f / (1.f + __expf(-zi));
            float fg = 1.f / (1.f + __expf(-zf));
            float og = 1.f / (1.f + __expf(-zo));
            c1 = fmaf(fg, c1, ig * zg);
            float hn = og * c1;
            Aout[pw1] = cvt_tf32(hn);
            if (hseq) hseq[(size_t)row1 * (TT * UU) + (size_t)t * UU + u] = hn;
            if (hlast && t == TT - 1) hlast[row1 * UU + u] = hn;
        }

        if (t != TT - 1)
            grid_barrier_step((unsigned)(t + 1));
    }
}

// ===========================================================================
// LayerNorm + tanh
// ===========================================================================
__global__ __launch_bounds__(256, 4)
void ln_tanh_kernel(const float* __restrict__ in, float* __restrict__ out,
                    const float* __restrict__ gamma, const float* __restrict__ beta)
{
    const int row = blockIdx.x;
    const float* xr = in + (size_t)row * UU;
    float* yr = out + (size_t)row * UU;
    const int tid = threadIdx.x;

    float v[4];
    float s = 0.f, sq = 0.f;
    #pragma unroll
    for (int q = 0; q < 4; q++) {
        v[q] = xr[tid + q * 256];
        s += v[q];
        sq = fmaf(v[q], v[q], sq);
    }
    __shared__ float sm1[8], sm2[8];
    #pragma unroll
    for (int o = 16; o > 0; o >>= 1) {
        s  += __shfl_xor_sync(0xffffffffu, s, o);
        sq += __shfl_xor_sync(0xffffffffu, sq, o);
    }
    if ((tid & 31) == 0) { sm1[tid >> 5] = s; sm2[tid >> 5] = sq; }
    __syncthreads();
    __shared__ float s_mu, s_inv;
    if (tid == 0) {
        float ts = 0.f, tq = 0.f;
        #pragma unroll
        for (int w = 0; w < 8; w++) { ts += sm1[w]; tq += sm2[w]; }
        float mu = ts * (1.f / UU);
        float var = tq * (1.f / UU) - mu * mu;
        s_mu = mu;
        s_inv = rsqrtf(var + LN_EPS);
    }
    __syncthreads();
    float mu = s_mu, inv = s_inv;
    #pragma unroll
    for (int q = 0; q < 4; q++) {
        int idx = tid + q * 256;
        float y = (v[q] - mu) * inv * gamma[idx] + beta[idx];
        yr[idx] = tanhf(y);
    }
}

// ===========================================================================
// Per-layer init: zero packed h0 (ping), reset barrier counter + epoch
// ===========================================================================
__global__ void init_kernel(float* __restrict__ hH)
{
    int i = blockIdx.x * blockDim.x + threadIdx.x;
    if (i == 0) { g_barcnt[0] = 0u; g_epoch[0] = 0u; }
    if (i < 128 * 4 * 32 * 4) hH[i] = 0.f;
}

// ===========================================================================
// Launch: 10 graph nodes.  Order per layer: pack, init, gemm, lstm, ln
// ===========================================================================
extern "C" void kernel_launch(void* const* d_in, const int* in_sizes, int n_in,
                              void* d_out, int out_size)
{
    const float* x      = (const float*)d_in[0];
    const float* W1     = (const float*)d_in[1];
    const float* R1     = (const float*)d_in[2];
    const float* b1     = (const float*)d_in[3];
    const float* gamma1 = (const float*)d_in[4];
    const float* beta1  = (const float*)d_in[5];
    const float* W2     = (const float*)d_in[6];
    const float* R2     = (const float*)d_in[7];
    const float* b2     = (const float*)d_in[8];
    const float* gamma2 = (const float*)d_in[9];
    const float* beta2  = (const float*)d_in[10];
    float* out = (float*)d_out;

    float *zx, *hseq, *rp, *hpH0, *hpH1, *hlast;
    cudaGetSymbolAddress((void**)&zx,    g_zx);
    cudaGetSymbolAddress((void**)&hseq,  g_hseq);
    cudaGetSymbolAddress((void**)&rp,    g_rp2);
    cudaGetSymbolAddress((void**)&hlast, g_hlast);
    { void* p; cudaGetSymbolAddress(&p, g_hp_hi); hpH0 = (float*)p; hpH1 = hpH0 + 128 * 4 * 32 * 4; }

    cudaFuncSetAttribute(gemm_tf32_kernel,
                         cudaFuncAttributeMaxDynamicSharedMemorySize, GEMM_SMEM_BYTES);
    cudaFuncSetAttribute(lstm_mma_kernel,
                         cudaFuncAttributeMaxDynamicSharedMemorySize, LSTM_SMEM_BYTES);

    const int M = BB * TT;                       // 32768
    const dim3 ggrid(G4 / 128, M / 128);         // (32, 256)
    const int initg = (128 * 4 * 32 * 4 + 255) / 256;
    const int packg = (128 * 128 * 2 * 32) / 256;

    // ---- Layer 1 ----
    pack_r2_kernel<<<packg, 256>>>(R1, rp);
    init_kernel<<<initg, 256>>>(hpH0);
    gemm_tf32_kernel<<<ggrid, 256, GEMM_SMEM_BYTES>>>(x, W1, b1, zx, M, G4, DD);
    lstm_mma_kernel<<<128, 256, LSTM_SMEM_BYTES>>>(zx, rp, hpH0, hpH1, hseq, (float*)nullptr);
    ln_tanh_kernel<<<M, 256>>>(hseq, hseq, gamma1, beta1);

    // ---- Layer 2 ----
    pack_r2_kernel<<<packg, 256>>>(R2, rp);
    init_kernel<<<initg, 256>>>(hpH0);
    gemm_tf32_kernel<<<ggrid, 256, GEMM_SMEM_BYTES>>>(hseq, W2, b2, zx, M, G4, UU);
    lstm_mma_kernel<<<128, 256, LSTM_SMEM_BYTES>>>(zx, rp, hpH0, hpH1, (float*)nullptr, hlast);
    ln_tanh_kernel<<<BB, 256>>>(hlast, out, gamma2, beta2);
}

// round 11
// speedup vs baseline: 5.6135x; 1.1950x over previous
#include <cuda_runtime.h>
#include <math.h>
#include <stdint.h>

// Problem constants
#define BB 64
#define TT 512
#define DD 512
#define UU 1024
#define G4 4096          // 4*UU
#define LN_EPS 1e-3f

// ---------------------------------------------------------------------------
// Scratch (device globals — no allocation allowed)
// ---------------------------------------------------------------------------
__device__ float g_zx[(size_t)BB * TT * G4];     // 512 MiB, reused by both layers
__device__ float g_hseq[(size_t)BB * TT * UU];   // 128 MiB
// packed R (tf32-hi, B-frag pair layout): [block 128][kt 128][pair 2][lane 32][4]
__device__ float g_rp2[(size_t)128 * 128 * 2 * 32 * 4];   // 16 MiB
// packed h hi (A-frag layout): [128 ktiles][4 mtiles][32 lanes][4 slots], ping/pong
__device__ float g_hp_hi[2][128 * 4 * 32 * 4];   // 256KB each
__device__ float g_hlast[BB * UU];
__device__ __align__(128) unsigned g_barcnt[32]; // arrival counter (own line)
__device__ __align__(128) unsigned g_epoch[32];  // epoch flag (own line)

// ---------------------------------------------------------------------------
// Helpers
// ---------------------------------------------------------------------------
__device__ __forceinline__ float cvt_tf32(float a) {
    float r;
    asm("cvt.rna.tf32.f32 %0, %1;" : "=f"(r) : "f"(a));
    return r;
}

__device__ __forceinline__ void cp16(void* s, const void* g) {
    uint32_t sa = (uint32_t)__cvta_generic_to_shared(s);
    asm volatile("cp.async.cg.shared.global [%0], [%1], 16;" :: "r"(sa), "l"(g));
}
#define CP_COMMIT()  asm volatile("cp.async.commit_group;" ::: "memory")
#define CP_WAIT(n)   asm volatile("cp.async.wait_group %0;" :: "n"(n) : "memory")

__device__ __forceinline__ void bar_pair(int id) {
    asm volatile("bar.sync %0, 64;" :: "r"(id) : "memory");
}

#define MMA_TF32(d, a, b0v, b1v) \
    asm volatile("mma.sync.aligned.m16n8k8.row.col.f32.tf32.tf32.f32 " \
        "{%0,%1,%2,%3}, {%4,%5,%6,%7}, {%8,%9}, {%0,%1,%2,%3};" \
        : "+f"((d)[0]), "+f"((d)[1]), "+f"((d)[2]), "+f"((d)[3]) \
        : "r"((a)[0]), "r"((a)[1]), "r"((a)[2]), "r"((a)[3]), \
          "r"(b0v), "r"(b1v))

#define MMA_T4(d, av, b0v, b1v) \
    asm volatile("mma.sync.aligned.m16n8k8.row.col.f32.tf32.tf32.f32 " \
        "{%0,%1,%2,%3}, {%4,%5,%6,%7}, {%8,%9}, {%0,%1,%2,%3};" \
        : "+f"((d)[0]), "+f"((d)[1]), "+f"((d)[2]), "+f"((d)[3]) \
        : "r"(__float_as_uint((av).x)), "r"(__float_as_uint((av).y)), \
          "r"(__float_as_uint((av).z)), "r"(__float_as_uint((av).w)), \
          "r"(__float_as_uint(b0v)), "r"(__float_as_uint(b1v)))

// ===========================================================================
// Pack R (tf32-hi) into per-block smem-ready B-frag pair layout.
// ===========================================================================
__global__ __launch_bounds__(256)
void pack_r2_kernel(const float* __restrict__ R, float* __restrict__ Rp)
{
    int i = blockIdx.x * blockDim.x + threadIdx.x;   // float4 index
    int lane = i & 31;
    int p    = (i >> 5) & 1;
    int kt   = (i >> 6) & 127;
    int b    = i >> 13;
    int r0 = kt * 8 + (lane & 3);
    int j  = lane >> 2;
    int c0 = (2 * p) * UU + b * 8 + j;
    int c1 = (2 * p + 1) * UU + b * 8 + j;
    float4 o;
    o.x = cvt_tf32(__ldg(&R[(size_t)r0 * G4 + c0]));
    o.y = cvt_tf32(__ldg(&R[(size_t)(r0 + 4) * G4 + c0]));
    o.z = cvt_tf32(__ldg(&R[(size_t)r0 * G4 + c1]));
    o.w = cvt_tf32(__ldg(&R[(size_t)(r0 + 4) * G4 + c1]));
    *(float4*)&Rp[(size_t)i * 4] = o;
}

// ===========================================================================
// 2xTF32 GEMM (Ah*Bh + Ah*Bl) with cp.async double-buffering, fused W access:
//   C[M,N] = A[M,K] @ W[K,N] + b
// Block 128x128, BK=32, 256 threads (8 warps: 4m x 2n, warp tile 32x64).
// ===========================================================================
#define GBK   32
#define A_LD  36                  // floats/row (bank (g*4+ii)%32 distinct)
#define B_LD  136                 // floats/row: 128 data + 8 pad (136%32==8)
#define ASZ   (128 * A_LD)        // 4608 floats
#define BSZ   (GBK * B_LD)        // 4352 floats
#define GEMM_SMEM_BYTES (2 * (ASZ + BSZ) * 4)   // 71680 B

__global__ __launch_bounds__(256, 2)
void gemm_tf32_kernel(const float* __restrict__ A, const float* __restrict__ W,
                      const float* __restrict__ bias, float* __restrict__ C,
                      int M, int N, int K)
{
    extern __shared__ float sm[];
    float* Asm[2] = { sm, sm + ASZ };
    float* Bsm[2] = { sm + 2 * ASZ, sm + 2 * ASZ + BSZ };

    const int tid  = threadIdx.x;
    const int m0   = blockIdx.y * 128;
    const int n0   = blockIdx.x * 128;
    const int lane = tid & 31, wid = tid >> 5;
    const int wm   = (wid & 3) * 32;
    const int wn   = (wid >> 2) * 64;
    const int g    = lane >> 2, ii = lane & 3;

    const int a_r = tid >> 3, a_c = (tid & 7) * 4;     // + p*32 rows
    const int b_r = tid >> 5, b_c = (tid & 31) * 4;    // + p*8 rows

    float acc[2][8][4];
    #pragma unroll
    for (int mi = 0; mi < 2; mi++)
        #pragma unroll
        for (int ni = 0; ni < 8; ni++)
            #pragma unroll
            for (int q = 0; q < 4; q++) acc[mi][ni][q] = 0.f;

    const int nk = K >> 5;

    {
        #pragma unroll
        for (int p = 0; p < 4; p++)
            cp16(&Asm[0][(a_r + p * 32) * A_LD + a_c],
                 &A[(size_t)(m0 + a_r + p * 32) * K + a_c]);
        #pragma unroll
        for (int p = 0; p < 4; p++)
            cp16(&Bsm[0][(b_r + p * 8) * B_LD + b_c],
                 &W[(size_t)(b_r + p * 8) * N + n0 + b_c]);
        CP_COMMIT();
    }

    for (int ch = 0; ch < nk; ch++) {
        const int buf = ch & 1;
        if (ch + 1 < nk) {
            const int k0 = (ch + 1) << 5;
            #pragma unroll
            for (int p = 0; p < 4; p++)
                cp16(&Asm[buf ^ 1][(a_r + p * 32) * A_LD + a_c],
                     &A[(size_t)(m0 + a_r + p * 32) * K + k0 + a_c]);
            #pragma unroll
            for (int p = 0; p < 4; p++)
                cp16(&Bsm[buf ^ 1][(b_r + p * 8) * B_LD + b_c],
                     &W[(size_t)(k0 + b_r + p * 8) * N + n0 + b_c]);
            CP_COMMIT();
            CP_WAIT(1);
        } else {
            CP_WAIT(0);
        }
        __syncthreads();

        const float* Ab = Asm[buf];
        const float* Bb = Bsm[buf];
        #pragma unroll
        for (int ks = 0; ks < 4; ks++) {
            const int kb = ks * 8;
            uint32_t ah[2][4];
            #pragma unroll
            for (int mi = 0; mi < 2; mi++) {
                int r0 = (wm + mi * 16 + g) * A_LD + kb + ii;
                int r8 = r0 + 8 * A_LD;
                ah[mi][0] = __float_as_uint(cvt_tf32(Ab[r0]));
                ah[mi][1] = __float_as_uint(cvt_tf32(Ab[r8]));
                ah[mi][2] = __float_as_uint(cvt_tf32(Ab[r0 + 4]));
                ah[mi][3] = __float_as_uint(cvt_tf32(Ab[r8 + 4]));
            }
            #pragma unroll
            for (int ni = 0; ni < 8; ni++) {
                int nb = wn + ni * 8 + g;
                float w0 = Bb[(kb + ii) * B_LD + nb];
                float w1 = Bb[(kb + ii + 4) * B_LD + nb];
                float bh0f = cvt_tf32(w0), bh1f = cvt_tf32(w1);
                uint32_t bh0 = __float_as_uint(bh0f);
                uint32_t bh1 = __float_as_uint(bh1f);
                uint32_t bl0 = __float_as_uint(cvt_tf32(w0 - bh0f));
                uint32_t bl1 = __float_as_uint(cvt_tf32(w1 - bh1f));
                #pragma unroll
                for (int mi = 0; mi < 2; mi++) {
                    MMA_TF32(acc[mi][ni], ah[mi], bh0, bh1);
                    MMA_TF32(acc[mi][ni], ah[mi], bl0, bl1);
                }
            }
        }
        __syncthreads();
    }

    #pragma unroll
    for (int mi = 0; mi < 2; mi++) {
        int r0 = m0 + wm + mi * 16 + g;
        #pragma unroll
        for (int ni = 0; ni < 8; ni++) {
            int cc = n0 + wn + ni * 8 + ii * 2;
            float b0v = __ldg(&bias[cc]);
            float b1v = __ldg(&bias[cc + 1]);
            float2 o0 = make_float2(acc[mi][ni][0] + b0v, acc[mi][ni][1] + b1v);
            float2 o1 = make_float2(acc[mi][ni][2] + b0v, acc[mi][ni][3] + b1v);
            *(float2*)&C[(size_t)r0 * N + cc] = o0;
            *(float2*)&C[(size_t)(r0 + 8) * N + cc] = o1;
        }
    }
}

// ===========================================================================
// Fast grid barrier
// ===========================================================================
__device__ __forceinline__ void grid_barrier_step(unsigned t1)
{
    __syncthreads();
    if (threadIdx.x == 0) {
        unsigned old;
        asm volatile("atom.release.gpu.global.add.u32 %0, [%1], %2;"
                     : "=r"(old) : "l"(&g_barcnt[0]), "r"(1u) : "memory");
        if (old + 1u == 128u * t1) {
            asm volatile("st.release.gpu.global.u32 [%0], %1;"
                         :: "l"(&g_epoch[0]), "r"(t1) : "memory");
        } else {
            unsigned e;
            do {
                __nanosleep(32);
                asm volatile("ld.acquire.gpu.global.u32 %0, [%1];"
                             : "=r"(e) : "l"(&g_epoch[0]) : "memory");
            } while (e < t1);
        }
    }
    __syncthreads();
}

// ===========================================================================
// Persistent LSTM layer, pure-TF32 recurrence, pair-scoped async pipeline.
// 128 blocks x 256 threads (8 warps: wm=wid&3, wn=wid>>2).
// R (tf32-hi) in SMEM (128 KB, once). Warp pair (wm,*) shares a 3-slot ring
// of 8-ktile A chunks staged via cp.async, synced with named barrier wm+1.
// No block-wide syncs inside the K loop. 4 MMA accumulator chains per warp.
// ===========================================================================
#define LSTM_SMEM_BYTES ((32768 + 4 * 3 * 1024) * 4)   // 180224 B

__global__ __launch_bounds__(256, 1)
void lstm_mma_kernel(const float* __restrict__ zx,     // [B*TT][G4], row=b*TT+t
                     const float* __restrict__ Rp,     // packed tf32-hi
                     float* __restrict__ hpH0, float* __restrict__ hpH1,
                     float* __restrict__ hseq,         // [B][TT][UU] or null
                     float* __restrict__ hlast)        // [B][UU] or null
{
    extern __shared__ float dsm[];
    float* Rs = dsm;                       // 32768 floats
    __shared__ float zs[64][33];

    const int tid  = threadIdx.x;
    const int b    = blockIdx.x;           // 0..127
    const int u0   = b * 8;
    const int lane = tid & 31, wid = tid >> 5;
    const int wm   = wid & 3;
    const int wn   = wid >> 2;
    const int lane4 = lane * 4;
    const int pt   = (wn << 5) | lane;     // pair-thread id 0..63
    float* pbuf = dsm + 32768 + wm * 3 * 1024;   // 3 slots x 1024 floats

    // load this block's packed R into smem (once)
    {
        const float4* src = (const float4*)(Rp + (size_t)b * 32768);
        float4* dst = (float4*)Rs;
        #pragma unroll
        for (int q = 0; q < 32; q++)
            dst[q * 256 + tid] = __ldg(&src[q * 256 + tid]);
    }
    __syncthreads();

    // gating ownership
    const int row0 = tid >> 3, j0 = tid & 7;
    const int row1 = row0 + 32;
    float c0 = 0.f, c1 = 0.f;

    auto pidx = [&](int row) {
        int mt = row >> 4, mm = row & 15;
        int lw = (mm & 7) * 4 + (j0 & 3);
        int slot = ((mm >> 3) & 1) + ((j0 >> 2) << 1);
        return (b * 4 + mt) * 128 + lw * 4 + slot;
    };
    const int pw0 = pidx(row0);
    const int pw1 = pidx(row1);

    for (int t = 0; t < TT; t++) {
        const float* Ain  = (t & 1) ? hpH1 : hpH0;
        float*       Aout = (t & 1) ? hpH0 : hpH1;

        // zx prefetch (gate inputs, independent of h)
        float zx0[4], zx1[4];
        {
            const float* z0 = zx + (size_t)row0 * (TT * G4) + (size_t)t * G4 + u0 + j0;
            const float* z1 = zx + (size_t)row1 * (TT * G4) + (size_t)t * G4 + u0 + j0;
            #pragma unroll
            for (int g = 0; g < 4; g++) { zx0[g] = __ldcs(z0 + g * UU); zx1[g] = __ldcs(z1 + g * UU); }
        }

        float accA0[4] = {0.f,0.f,0.f,0.f}, accB0[4] = {0.f,0.f,0.f,0.f};
        float accA1[4] = {0.f,0.f,0.f,0.f}, accB1[4] = {0.f,0.f,0.f,0.f};

        // stage chunk ch (8 ktiles, 4 KB) into slot, by the 64 pair threads
        auto stage = [&](int ch, int slot) {
            float* dstb = pbuf + slot * 1024;
            #pragma unroll
            for (int q = 0; q < 4; q++) {
                int idx = q * 64 + pt;             // float4 index 0..255
                int i = idx >> 5, j = idx & 31;
                cp16(&dstb[idx * 4], &Ain[((ch * 8 + i) * 4 + wm) * 128 + j * 4]);
            }
            CP_COMMIT();
        };

        stage(0, 0);
        stage(1, 1);

        for (int ch = 0; ch < 16; ch++) {
            if (ch == 15) { CP_WAIT(0); } else { CP_WAIT(1); }
            bar_pair(wm + 1);                      // pair data ready (and slot
                                                   // consumed 3 chunks ago is free)
            const float* sb = pbuf + (ch - (ch / 3) * 3) * 1024;   // ch % 3
            #pragma unroll
            for (int i = 0; i < 8; i += 2) {
                float4 a4e = *(const float4*)&sb[i * 128 + lane4];
                float4 a4o = *(const float4*)&sb[(i + 1) * 128 + lane4];
                int ktg = ch * 8 + i;
                float4 r4e = *(const float4*)&Rs[(ktg * 2 + wn) * 128 + lane4];
                float4 r4o = *(const float4*)&Rs[((ktg + 1) * 2 + wn) * 128 + lane4];
                MMA_T4(accA0, a4e, r4e.x, r4e.y);
                MMA_T4(accA1, a4e, r4e.z, r4e.w);
                MMA_T4(accB0, a4o, r4o.x, r4o.y);
                MMA_T4(accB1, a4o, r4o.z, r4o.w);
            }
            if (ch + 2 < 16) {
                int s2 = ch + 2;
                stage(s2, s2 - (s2 / 3) * 3);
            }
        }

        float acc0[4], acc1[4];
        #pragma unroll
        for (int q = 0; q < 4; q++) { acc0[q] = accA0[q] + accB0[q]; acc1[q] = accA1[q] + accB1[q]; }

        // scatter z fragments to smem
        {
            int rr  = wm * 16 + (lane >> 2);
            int c0i = (2 * wn) * 8 + (lane & 3) * 2;
            int c1i = (2 * wn + 1) * 8 + (lane & 3) * 2;
            zs[rr][c0i]         = acc0[0];
            zs[rr][c0i + 1]     = acc0[1];
            zs[rr + 8][c0i]     = acc0[2];
            zs[rr + 8][c0i + 1] = acc0[3];
            zs[rr][c1i]         = acc1[0];
            zs[rr][c1i + 1]     = acc1[1];
            zs[rr + 8][c1i]     = acc1[2];
            zs[rr + 8][c1i + 1] = acc1[3];
        }
        __syncthreads();

        // gating (c in registers); write tf32-hi packed h + exact hseq/hlast
        {
            int u = u0 + j0;
            float zi = zs[row0][j0]      + zx0[0];
            float zf = zs[row0][8 + j0]  + zx0[1];
            float zg = zs[row0][16 + j0] + zx0[2];
            float zo = zs[row0][24 + j0] + zx0[3];
            float ig = 1.f / (1.f + __expf(-zi));
            float fg = 1.f / (1.f + __expf(-zf));
            float og = 1.f / (1.f + __expf(-zo));
            c0 = fmaf(fg, c0, ig * zg);
            float hn = og * c0;
            Aout[pw0] = cvt_tf32(hn);
            if (hseq) hseq[(size_t)row0 * (TT * UU) + (size_t)t * UU + u] = hn;
            if (hlast && t == TT - 1) hlast[row0 * UU + u] = hn;
        }
        {
            int u = u0 + j0;
            float zi = zs[row1][j0]      + zx1[0];
            float zf = zs[row1][8 + j0]  + zx1[1];
            float zg = zs[row1][16 + j0] + zx1[2];
            float zo = zs[row1][24 + j0] + zx1[3];
            float ig = 1.f / (1.f + __expf(-zi));
            float fg = 1.f / (1.f + __expf(-zf));
            float og = 1.f / (1.f + __expf(-zo));
            c1 = fmaf(fg, c1, ig * zg);
            float hn = og * c1;
            Aout[pw1] = cvt_tf32(hn);
            if (hseq) hseq[(size_t)row1 * (TT * UU) + (size_t)t * UU + u] = hn;
            if (hlast && t == TT - 1) hlast[row1 * UU + u] = hn;
        }

        if (t != TT - 1)
            grid_barrier_step((unsigned)(t + 1));
    }
}

// ===========================================================================
// LayerNorm + tanh
// ===========================================================================
__global__ __launch_bounds__(256, 4)
void ln_tanh_kernel(const float* __restrict__ in, float* __restrict__ out,
                    const float* __restrict__ gamma, const float* __restrict__ beta)
{
    const int row = blockIdx.x;
    const float* xr = in + (size_t)row * UU;
    float* yr = out + (size_t)row * UU;
    const int tid = threadIdx.x;

    float v[4];
    float s = 0.f, sq = 0.f;
    #pragma unroll
    for (int q = 0; q < 4; q++) {
        v[q] = xr[tid + q * 256];
        s += v[q];
        sq = fmaf(v[q], v[q], sq);
    }
    __shared__ float sm1[8], sm2[8];
    #pragma unroll
    for (int o = 16; o > 0; o >>= 1) {
        s  += __shfl_xor_sync(0xffffffffu, s, o);
        sq += __shfl_xor_sync(0xffffffffu, sq, o);
    }
    if ((tid & 31) == 0) { sm1[tid >> 5] = s; sm2[tid >> 5] = sq; }
    __syncthreads();
    __shared__ float s_mu, s_inv;
    if (tid == 0) {
        float ts = 0.f, tq = 0.f;
        #pragma unroll
        for (int w = 0; w < 8; w++) { ts += sm1[w]; tq += sm2[w]; }
        float mu = ts * (1.f / UU);
        float var = tq * (1.f / UU) - mu * mu;
        s_mu = mu;
        s_inv = rsqrtf(var + LN_EPS);
    }
    __syncthreads();
    float mu = s_mu, inv = s_inv;
    #pragma unroll
    for (int q = 0; q < 4; q++) {
        int idx = tid + q * 256;
        float y = (v[q] - mu) * inv * gamma[idx] + beta[idx];
        yr[idx] = tanhf(y);
    }
}

// ===========================================================================
// Per-layer init: zero packed h0 (ping), reset barrier counter + epoch
// ===========================================================================
__global__ void init_kernel(float* __restrict__ hH)
{
    int i = blockIdx.x * blockDim.x + threadIdx.x;
    if (i == 0) { g_barcnt[0] = 0u; g_epoch[0] = 0u; }
    if (i < 128 * 4 * 32 * 4) hH[i] = 0.f;
}

// ===========================================================================
// Launch: 10 graph nodes.  Order per layer: pack, init, gemm, lstm, ln
// ===========================================================================
extern "C" void kernel_launch(void* const* d_in, const int* in_sizes, int n_in,
                              void* d_out, int out_size)
{
    const float* x      = (const float*)d_in[0];
    const float* W1     = (const float*)d_in[1];
    const float* R1     = (const float*)d_in[2];
    const float* b1     = (const float*)d_in[3];
    const float* gamma1 = (const float*)d_in[4];
    const float* beta1  = (const float*)d_in[5];
    const float* W2     = (const float*)d_in[6];
    const float* R2     = (const float*)d_in[7];
    const float* b2     = (const float*)d_in[8];
    const float* gamma2 = (const float*)d_in[9];
    const float* beta2  = (const float*)d_in[10];
    float* out = (float*)d_out;

    float *zx, *hseq, *rp, *hpH0, *hpH1, *hlast;
    cudaGetSymbolAddress((void**)&zx,    g_zx);
    cudaGetSymbolAddress((void**)&hseq,  g_hseq);
    cudaGetSymbolAddress((void**)&rp,    g_rp2);
    cudaGetSymbolAddress((void**)&hlast, g_hlast);
    { void* p; cudaGetSymbolAddress(&p, g_hp_hi); hpH0 = (float*)p; hpH1 = hpH0 + 128 * 4 * 32 * 4; }

    cudaFuncSetAttribute(gemm_tf32_kernel,
                         cudaFuncAttributeMaxDynamicSharedMemorySize, GEMM_SMEM_BYTES);
    cudaFuncSetAttribute(lstm_mma_kernel,
                         cudaFuncAttributeMaxDynamicSharedMemorySize, LSTM_SMEM_BYTES);

    const int M = BB * TT;                       // 32768
    const dim3 ggrid(G4 / 128, M / 128);         // (32, 256)
    const int initg = (128 * 4 * 32 * 4 + 255) / 256;
    const int packg = (128 * 128 * 2 * 32) / 256;

    // ---- Layer 1 ----
    pack_r2_kernel<<<packg, 256>>>(R1, rp);
    init_kernel<<<initg, 256>>>(hpH0);
    gemm_tf32_kernel<<<ggrid, 256, GEMM_SMEM_BYTES>>>(x, W1, b1, zx, M, G4, DD);
    lstm_mma_kernel<<<128, 256, LSTM_SMEM_BYTES>>>(zx, rp, hpH0, hpH1, hseq, (float*)nullptr);
    ln_tanh_kernel<<<M, 256>>>(hseq, hseq, gamma1, beta1);

    // ---- Layer 2 ----
    pack_r2_kernel<<<packg, 256>>>(R2, rp);
    init_kernel<<<initg, 256>>>(hpH0);
    gemm_tf32_kernel<<<ggrid, 256, GEMM_SMEM_BYTES>>>(hseq, W2, b2, zx, M, G4, UU);
    lstm_mma_kernel<<<128, 256, LSTM_SMEM_BYTES>>>(zx, rp, hpH0, hpH1, (float*)nullptr, hlast);
    ln_tanh_kernel<<<BB, 256>>>(hlast, out, gamma2, beta2);
}

// round 12
// speedup vs baseline: 6.2765x; 1.1181x over previous
#include <cuda_runtime.h>
#include <math.h>
#include <stdint.h>

// Problem constants
#define BB 64
#define TT 512
#define DD 512
#define UU 1024
#define G4 4096          // 4*UU
#define LN_EPS 1e-3f

// ---------------------------------------------------------------------------
// Scratch (device globals — no allocation allowed)
// ---------------------------------------------------------------------------
__device__ float g_zx[(size_t)BB * TT * G4];     // 512 MiB, reused by both layers
__device__ float g_hseq[(size_t)BB * TT * UU];   // 128 MiB
// packed R^T as A-frags: [block 128][kt 128][mt 2][lane 32][4]  (tf32-hi)
__device__ float g_rp2[(size_t)128 * 128 * 2 * 32 * 4];   // 16 MiB
// packed h^T as B-frags: [kt 128][nt 8][lane 32][2 slots], ping/pong
__device__ float g_hp_hi[2][128 * 8 * 32 * 2];   // 256KB each
__device__ float g_hlast[BB * UU];
__device__ __align__(128) unsigned g_barcnt[32]; // arrival counter (own line)
__device__ __align__(128) unsigned g_epoch[32];  // epoch flag (own line)

// ---------------------------------------------------------------------------
// Helpers
// ---------------------------------------------------------------------------
__device__ __forceinline__ float cvt_tf32(float a) {
    float r;
    asm("cvt.rna.tf32.f32 %0, %1;" : "=f"(r) : "f"(a));
    return r;
}

__device__ __forceinline__ void cp16(void* s, const void* g) {
    uint32_t sa = (uint32_t)__cvta_generic_to_shared(s);
    asm volatile("cp.async.cg.shared.global [%0], [%1], 16;" :: "r"(sa), "l"(g));
}
#define CP_COMMIT()  asm volatile("cp.async.commit_group;" ::: "memory")
#define CP_WAIT(n)   asm volatile("cp.async.wait_group %0;" :: "n"(n) : "memory")

#define MMA_TF32(d, a, b0v, b1v) \
    asm volatile("mma.sync.aligned.m16n8k8.row.col.f32.tf32.tf32.f32 " \
        "{%0,%1,%2,%3}, {%4,%5,%6,%7}, {%8,%9}, {%0,%1,%2,%3};" \
        : "+f"((d)[0]), "+f"((d)[1]), "+f"((d)[2]), "+f"((d)[3]) \
        : "r"((a)[0]), "r"((a)[1]), "r"((a)[2]), "r"((a)[3]), \
          "r"(b0v), "r"(b1v))

// ===========================================================================
// Pack R^T (tf32-hi) into per-block A-frag layout:
//   A[m][k] = R[k][gate*UU + b*8 + j],  m = gate*8+j (0..31), mt = m/16
//   a0=A[mt*16+g][kt*8+ii]  a1=A[mt*16+g+8][..]  a2=A[..][kt*8+ii+4]  a3=...
//   Rp[b*32768 + ((kt*2+mt)*32 + lane)*4] = {a0,a1,a2,a3}
// ===========================================================================
__global__ __launch_bounds__(256)
void pack_r3_kernel(const float* __restrict__ R, float* __restrict__ Rp)
{
    int i = blockIdx.x * blockDim.x + threadIdx.x;   // float4 index (2^20 total)
    int lane = i & 31;
    int mt   = (i >> 5) & 1;
    int kt   = (i >> 6) & 127;
    int b    = i >> 13;
    int g  = lane >> 2, ii = lane & 3;
    int m0 = mt * 16 + g, m1 = m0 + 8;
    int col0 = (m0 >> 3) * UU + b * 8 + (m0 & 7);
    int col1 = (m1 >> 3) * UU + b * 8 + (m1 & 7);
    int r0 = kt * 8 + ii;
    float4 o;
    o.x = cvt_tf32(__ldg(&R[(size_t)r0 * G4 + col0]));
    o.y = cvt_tf32(__ldg(&R[(size_t)r0 * G4 + col1]));
    o.z = cvt_tf32(__ldg(&R[(size_t)(r0 + 4) * G4 + col0]));
    o.w = cvt_tf32(__ldg(&R[(size_t)(r0 + 4) * G4 + col1]));
    *(float4*)&Rp[(size_t)i * 4] = o;
}

// ===========================================================================
// 2xTF32 GEMM (Ah*Bh + Ah*Bl), cp.async double-buffered (unchanged from R11)
// ===========================================================================
#define GBK   32
#define A_LD  36
#define B_LD  136
#define ASZ   (128 * A_LD)
#define BSZ   (GBK * B_LD)
#define GEMM_SMEM_BYTES (2 * (ASZ + BSZ) * 4)   // 71680 B

__global__ __launch_bounds__(256, 2)
void gemm_tf32_kernel(const float* __restrict__ A, const float* __restrict__ W,
                      const float* __restrict__ bias, float* __restrict__ C,
                      int M, int N, int K)
{
    extern __shared__ float sm[];
    float* Asm[2] = { sm, sm + ASZ };
    float* Bsm[2] = { sm + 2 * ASZ, sm + 2 * ASZ + BSZ };

    const int tid  = threadIdx.x;
    const int m0   = blockIdx.y * 128;
    const int n0   = blockIdx.x * 128;
    const int lane = tid & 31, wid = tid >> 5;
    const int wm   = (wid & 3) * 32;
    const int wn   = (wid >> 2) * 64;
    const int g    = lane >> 2, ii = lane & 3;

    const int a_r = tid >> 3, a_c = (tid & 7) * 4;
    const int b_r = tid >> 5, b_c = (tid & 31) * 4;

    float acc[2][8][4];
    #pragma unroll
    for (int mi = 0; mi < 2; mi++)
        #pragma unroll
        for (int ni = 0; ni < 8; ni++)
            #pragma unroll
            for (int q = 0; q < 4; q++) acc[mi][ni][q] = 0.f;

    const int nk = K >> 5;

    {
        #pragma unroll
        for (int p = 0; p < 4; p++)
            cp16(&Asm[0][(a_r + p * 32) * A_LD + a_c],
                 &A[(size_t)(m0 + a_r + p * 32) * K + a_c]);
        #pragma unroll
        for (int p = 0; p < 4; p++)
            cp16(&Bsm[0][(b_r + p * 8) * B_LD + b_c],
                 &W[(size_t)(b_r + p * 8) * N + n0 + b_c]);
        CP_COMMIT();
    }

    for (int ch = 0; ch < nk; ch++) {
        const int buf = ch & 1;
        if (ch + 1 < nk) {
            const int k0 = (ch + 1) << 5;
            #pragma unroll
            for (int p = 0; p < 4; p++)
                cp16(&Asm[buf ^ 1][(a_r + p * 32) * A_LD + a_c],
                     &A[(size_t)(m0 + a_r + p * 32) * K + k0 + a_c]);
            #pragma unroll
            for (int p = 0; p < 4; p++)
                cp16(&Bsm[buf ^ 1][(b_r + p * 8) * B_LD + b_c],
                     &W[(size_t)(k0 + b_r + p * 8) * N + n0 + b_c]);
            CP_COMMIT();
            CP_WAIT(1);
        } else {
            CP_WAIT(0);
        }
        __syncthreads();

        const float* Ab = Asm[buf];
        const float* Bb = Bsm[buf];
        #pragma unroll
        for (int ks = 0; ks < 4; ks++) {
            const int kb = ks * 8;
            uint32_t ah[2][4];
            #pragma unroll
            for (int mi = 0; mi < 2; mi++) {
                int r0 = (wm + mi * 16 + g) * A_LD + kb + ii;
                int r8 = r0 + 8 * A_LD;
                ah[mi][0] = __float_as_uint(cvt_tf32(Ab[r0]));
                ah[mi][1] = __float_as_uint(cvt_tf32(Ab[r8]));
                ah[mi][2] = __float_as_uint(cvt_tf32(Ab[r0 + 4]));
                ah[mi][3] = __float_as_uint(cvt_tf32(Ab[r8 + 4]));
            }
            #pragma unroll
            for (int ni = 0; ni < 8; ni++) {
                int nb = wn + ni * 8 + g;
                float w0 = Bb[(kb + ii) * B_LD + nb];
                float w1 = Bb[(kb + ii + 4) * B_LD + nb];
                float bh0f = cvt_tf32(w0), bh1f = cvt_tf32(w1);
                uint32_t bh0 = __float_as_uint(bh0f);
                uint32_t bh1 = __float_as_uint(bh1f);
                uint32_t bl0 = __float_as_uint(cvt_tf32(w0 - bh0f));
                uint32_t bl1 = __float_as_uint(cvt_tf32(w1 - bh1f));
                #pragma unroll
                for (int mi = 0; mi < 2; mi++) {
                    MMA_TF32(acc[mi][ni], ah[mi], bh0, bh1);
                    MMA_TF32(acc[mi][ni], ah[mi], bl0, bl1);
                }
            }
        }
        __syncthreads();
    }

    #pragma unroll
    for (int mi = 0; mi < 2; mi++) {
        int r0 = m0 + wm + mi * 16 + g;
        #pragma unroll
        for (int ni = 0; ni < 8; ni++) {
            int cc = n0 + wn + ni * 8 + ii * 2;
            float b0v = __ldg(&bias[cc]);
            float b1v = __ldg(&bias[cc + 1]);
            float2 o0 = make_float2(acc[mi][ni][0] + b0v, acc[mi][ni][1] + b1v);
            float2 o1 = make_float2(acc[mi][ni][2] + b0v, acc[mi][ni][3] + b1v);
            *(float2*)&C[(size_t)r0 * N + cc] = o0;
            *(float2*)&C[(size_t)(r0 + 8) * N + cc] = o1;
        }
    }
}

// ===========================================================================
// Fast grid barrier
// ===========================================================================
__device__ __forceinline__ void grid_barrier_step(unsigned t1)
{
    __syncthreads();
    if (threadIdx.x == 0) {
        unsigned old;
        asm volatile("atom.release.gpu.global.add.u32 %0, [%1], %2;"
                     : "=r"(old) : "l"(&g_barcnt[0]), "r"(1u) : "memory");
        if (old + 1u == 128u * t1) {
            asm volatile("st.release.gpu.global.u32 [%0], %1;"
                         :: "l"(&g_epoch[0]), "r"(t1) : "memory");
        } else {
            unsigned e;
            do {
                __nanosleep(32);
                asm volatile("ld.acquire.gpu.global.u32 %0, [%1];"
                             : "=r"(e) : "l"(&g_epoch[0]) : "memory");
            } while (e < t1);
        }
    }
    __syncthreads();
}

// ===========================================================================
// Persistent LSTM layer — TRANSPOSED recurrence: z^T = R^T · h^T.
// 128 blocks x 256 threads; warp w owns K-slice ktiles [16w, 16w+16).
// A = R^T A-frags in smem (128 KB, loaded once). B = h^T B-frags read
// directly from gmem/L2 (one coalesced ldcg.64 per thread per (kt,nt)).
// Partials reduced across warps via zsum smem (stride 72 = conflict-free).
// ===========================================================================
#define ZS_LD 72
#define LSTM_SMEM_BYTES ((32768 + 8 * 32 * ZS_LD) * 4)   // 204800 B

__global__ __launch_bounds__(256, 1)
void lstm_mma_kernel(const float* __restrict__ zx,     // [B*TT][G4], row=b*TT+t
                     const float* __restrict__ Rp,     // packed A-frags
                     float* __restrict__ hpH0, float* __restrict__ hpH1,
                     float* __restrict__ hseq,         // [B][TT][UU] or null
                     float* __restrict__ hlast)        // [B][UU] or null
{
    extern __shared__ float dsm[];
    float* Rs   = dsm;                     // 32768 floats
    float* zsum = dsm + 32768;             // 8*32*ZS_LD floats

    const int tid  = threadIdx.x;
    const int b    = blockIdx.x;           // 0..127
    const int u0   = b * 8;
    const int lane = tid & 31, wid = tid >> 5;
    const int g    = lane >> 2, ii = lane & 3;
    const int lane4 = lane * 4;
    const int ksl  = wid * 16;             // this warp's ktile base

    // load this block's packed R (A-frags) into smem, once
    {
        const float4* src = (const float4*)(Rp + (size_t)b * 32768);
        float4* dst = (float4*)Rs;
        #pragma unroll
        for (int q = 0; q < 32; q++)
            dst[q * 256 + tid] = __ldg(&src[q * 256 + tid]);
    }
    __syncthreads();

    // gating ownership: items (row0, u0+j0) and (row1, u0+j0)
    const int row0 = tid >> 3, j0 = tid & 7;
    const int row1 = row0 + 32;
    float c0 = 0.f, c1 = 0.f;

    // h^T B-frag write index (kt == b for this block's units)
    auto pidx = [&](int row) {
        return ((b * 8 + (row >> 3)) * 32 + (row & 7) * 4 + (j0 & 3)) * 2 + (j0 >> 2);
    };
    const int pw0 = pidx(row0);
    const int pw1 = pidx(row1);

    for (int t = 0; t < TT; t++) {
        const float* Ain  = (t & 1) ? hpH1 : hpH0;
        float*       Aout = (t & 1) ? hpH0 : hpH1;
        const float2* hp2 = (const float2*)Ain;

        // zx prefetch (gate inputs, independent of h)
        float zx0[4], zx1[4];
        {
            const float* z0 = zx + (size_t)row0 * (TT * G4) + (size_t)t * G4 + u0 + j0;
            const float* z1 = zx + (size_t)row1 * (TT * G4) + (size_t)t * G4 + u0 + j0;
            #pragma unroll
            for (int q = 0; q < 4; q++) { zx0[q] = __ldcs(z0 + q * UU); zx1[q] = __ldcs(z1 + q * UU); }
        }

        float acc[2][8][4];
        #pragma unroll
        for (int mt = 0; mt < 2; mt++)
            #pragma unroll
            for (int nt = 0; nt < 8; nt++)
                #pragma unroll
                for (int q = 0; q < 4; q++) acc[mt][nt][q] = 0.f;

        // B-frag double buffer: bbuf[buf][nt][2]
        uint32_t bbuf[2][8][2];
        #pragma unroll
        for (int nt = 0; nt < 8; nt++) {
            float2 v = __ldcg(&hp2[(ksl * 8 + nt) * 32 + lane]);
            bbuf[0][nt][0] = __float_as_uint(v.x);
            bbuf[0][nt][1] = __float_as_uint(v.y);
        }

        #pragma unroll
        for (int kt = 0; kt < 16; kt++) {
            const int cur = kt & 1;
            if (kt < 15) {
                #pragma unroll
                for (int nt = 0; nt < 8; nt++) {
                    float2 v = __ldcg(&hp2[((ksl + kt + 1) * 8 + nt) * 32 + lane]);
                    bbuf[cur ^ 1][nt][0] = __float_as_uint(v.x);
                    bbuf[cur ^ 1][nt][1] = __float_as_uint(v.y);
                }
            }
            uint32_t a0[4], a1[4];
            *(float4*)a0 = *(const float4*)&Rs[((ksl + kt) * 2 + 0) * 128 + lane4];
            *(float4*)a1 = *(const float4*)&Rs[((ksl + kt) * 2 + 1) * 128 + lane4];
            #pragma unroll
            for (int nt = 0; nt < 8; nt++) {
                MMA_TF32(acc[0][nt], a0, bbuf[cur][nt][0], bbuf[cur][nt][1]);
                MMA_TF32(acc[1][nt], a1, bbuf[cur][nt][0], bbuf[cur][nt][1]);
            }
        }

        // store partial z^T to zsum[w][m 32][n 64] (stride ZS_LD)
        #pragma unroll
        for (int mt = 0; mt < 2; mt++)
            #pragma unroll
            for (int nt = 0; nt < 8; nt++) {
                int off = (wid * 32 + mt * 16 + g) * ZS_LD + nt * 8 + ii * 2;
                *(float2*)&zsum[off] = make_float2(acc[mt][nt][0], acc[mt][nt][1]);
                *(float2*)&zsum[off + 8 * ZS_LD] = make_float2(acc[mt][nt][2], acc[mt][nt][3]);
            }
        __syncthreads();

        // reduce 8 warp partials for this thread's gating items
        float z0[4] = {0.f, 0.f, 0.f, 0.f};
        float z1[4] = {0.f, 0.f, 0.f, 0.f};
        #pragma unroll
        for (int w = 0; w < 8; w++) {
            int base = (w * 32 + j0) * ZS_LD;
            #pragma unroll
            for (int gq = 0; gq < 4; gq++) {
                z0[gq] += zsum[base + gq * 8 * ZS_LD + row0];
                z1[gq] += zsum[base + gq * 8 * ZS_LD + row1];
            }
        }

        // gating (c in registers); write h^T B-frag packed + exact hseq/hlast
        {
            int u = u0 + j0;
            float zi = z0[0] + zx0[0];
            float zf = z0[1] + zx0[1];
            float zg = z0[2] + zx0[2];
            float zo = z0[3] + zx0[3];
            float ig = 1.f / (1.f + __expf(-zi));
            float fg = 1.f / (1.f + __expf(-zf));
            float og = 1.f / (1.f + __expf(-zo));
            c0 = fmaf(fg, c0, ig * zg);
            float hn = og * c0;
            __stcg(&Aout[pw0], cvt_tf32(hn));
            if (hseq) hseq[(size_t)row0 * (TT * UU) + (size_t)t * UU + u] = hn;
            if (hlast && t == TT - 1) hlast[row0 * UU + u] = hn;
        }
        {
            int u = u0 + j0;
            float zi = z1[0] + zx1[0];
            float zf = z1[1] + zx1[1];
            float zg = z1[2] + zx1[2];
            float zo = z1[3] + zx1[3];
            float ig = 1.f / (1.f + __expf(-zi));
            float fg = 1.f / (1.f + __expf(-zf));
            float og = 1.f / (1.f + __expf(-zo));
            c1 = fmaf(fg, c1, ig * zg);
            float hn = og * c1;
            __stcg(&Aout[pw1], cvt_tf32(hn));
            if (hseq) hseq[(size_t)row1 * (TT * UU) + (size_t)t * UU + u] = hn;
            if (hlast && t == TT - 1) hlast[row1 * UU + u] = hn;
        }

        if (t != TT - 1)
            grid_barrier_step((unsigned)(t + 1));
    }
}

// ===========================================================================
// LayerNorm + tanh
// ===========================================================================
__global__ __launch_bounds__(256, 4)
void ln_tanh_kernel(const float* __restrict__ in, float* __restrict__ out,
                    const float* __restrict__ gamma, const float* __restrict__ beta)
{
    const int row = blockIdx.x;
    const float* xr = in + (size_t)row * UU;
    float* yr = out + (size_t)row * UU;
    const int tid = threadIdx.x;

    float v[4];
    float s = 0.f, sq = 0.f;
    #pragma unroll
    for (int q = 0; q < 4; q++) {
        v[q] = xr[tid + q * 256];
        s += v[q];
        sq = fmaf(v[q], v[q], sq);
    }
    __shared__ float sm1[8], sm2[8];
    #pragma unroll
    for (int o = 16; o > 0; o >>= 1) {
        s  += __shfl_xor_sync(0xffffffffu, s, o);
        sq += __shfl_xor_sync(0xffffffffu, sq, o);
    }
    if ((tid & 31) == 0) { sm1[tid >> 5] = s; sm2[tid >> 5] = sq; }
    __syncthreads();
    __shared__ float s_mu, s_inv;
    if (tid == 0) {
        float ts = 0.f, tq = 0.f;
        #pragma unroll
        for (int w = 0; w < 8; w++) { ts += sm1[w]; tq += sm2[w]; }
        float mu = ts * (1.f / UU);
        float var = tq * (1.f / UU) - mu * mu;
        s_mu = mu;
        s_inv = rsqrtf(var + LN_EPS);
    }
    __syncthreads();
    float mu = s_mu, inv = s_inv;
    #pragma unroll
    for (int q = 0; q < 4; q++) {
        int idx = tid + q * 256;
        float y = (v[q] - mu) * inv * gamma[idx] + beta[idx];
        yr[idx] = tanhf(y);
    }
}

// ===========================================================================
// Per-layer init: zero packed h0 (ping), reset barrier counter + epoch
// ===========================================================================
__global__ void init_kernel(float* __restrict__ hH)
{
    int i = blockIdx.x * blockDim.x + threadIdx.x;
    if (i == 0) { g_barcnt[0] = 0u; g_epoch[0] = 0u; }
    if (i < 128 * 8 * 32 * 2) hH[i] = 0.f;
}

// ===========================================================================
// Launch: 10 graph nodes.  Order per layer: pack, init, gemm, lstm, ln
// ===========================================================================
extern "C" void kernel_launch(void* const* d_in, const int* in_sizes, int n_in,
                              void* d_out, int out_size)
{
    const float* x      = (const float*)d_in[0];
    const float* W1     = (const float*)d_in[1];
    const float* R1     = (const float*)d_in[2];
    const float* b1     = (const float*)d_in[3];
    const float* gamma1 = (const float*)d_in[4];
    const float* beta1  = (const float*)d_in[5];
    const float* W2     = (const float*)d_in[6];
    const float* R2     = (const float*)d_in[7];
    const float* b2     = (const float*)d_in[8];
    const float* gamma2 = (const float*)d_in[9];
    const float* beta2  = (const float*)d_in[10];
    float* out = (float*)d_out;

    float *zx, *hseq, *rp, *hpH0, *hpH1, *hlast;
    cudaGetSymbolAddress((void**)&zx,    g_zx);
    cudaGetSymbolAddress((void**)&hseq,  g_hseq);
    cudaGetSymbolAddress((void**)&rp,    g_rp2);
    cudaGetSymbolAddress((void**)&hlast, g_hlast);
    { void* p; cudaGetSymbolAddress(&p, g_hp_hi); hpH0 = (float*)p; hpH1 = hpH0 + 128 * 8 * 32 * 2; }

    cudaFuncSetAttribute(gemm_tf32_kernel,
                         cudaFuncAttributeMaxDynamicSharedMemorySize, GEMM_SMEM_BYTES);
    cudaFuncSetAttribute(lstm_mma_kernel,
                         cudaFuncAttributeMaxDynamicSharedMemorySize, LSTM_SMEM_BYTES);

    const int M = BB * TT;                       // 32768
    const dim3 ggrid(G4 / 128, M / 128);         // (32, 256)
    const int initg = (128 * 8 * 32 * 2 + 255) / 256;
    const int packg = (128 * 128 * 2 * 32) / 256;

    // ---- Layer 1 ----
    pack_r3_kernel<<<packg, 256>>>(R1, rp);
    init_kernel<<<initg, 256>>>(hpH0);
    gemm_tf32_kernel<<<ggrid, 256, GEMM_SMEM_BYTES>>>(x, W1, b1, zx, M, G4, DD);
    lstm_mma_kernel<<<128, 256, LSTM_SMEM_BYTES>>>(zx, rp, hpH0, hpH1, hseq, (float*)nullptr);
    ln_tanh_kernel<<<M, 256>>>(hseq, hseq, gamma1, beta1);

    // ---- Layer 2 ----
    pack_r3_kernel<<<packg, 256>>>(R2, rp);
    init_kernel<<<initg, 256>>>(hpH0);
    gemm_tf32_kernel<<<ggrid, 256, GEMM_SMEM_BYTES>>>(hseq, W2, b2, zx, M, G4, UU);
    lstm_mma_kernel<<<128, 256, LSTM_SMEM_BYTES>>>(zx, rp, hpH0, hpH1, (float*)nullptr, hlast);
    ln_tanh_kernel<<<BB, 256>>>(hlast, out, gamma2, beta2);
}

// round 13
// speedup vs baseline: 6.5058x; 1.0365x over previous
#include <cuda_runtime.h>
#include <math.h>
#include <stdint.h>

// Problem constants
#define BB 64
#define TT 512
#define DD 512
#define UU 1024
#define G4 4096          // 4*UU
#define LN_EPS 1e-3f

// ---------------------------------------------------------------------------
// Scratch (device globals — no allocation allowed)
// ---------------------------------------------------------------------------
__device__ float g_zx[(size_t)BB * TT * G4];     // 512 MiB, reused by both layers
__device__ float g_hseq[(size_t)BB * TT * UU];   // 128 MiB
// packed R^T as A-frags: [block 128][kt 128][mt 2][lane 32][4]  (tf32-hi)
__device__ float g_rp2[(size_t)128 * 128 * 2 * 32 * 4];   // 16 MiB
// packed h^T as B-frags: [kt 128][nt 8][lane 32][2 slots], ping/pong
__device__ float g_hp_hi[2][128 * 8 * 32 * 2];   // 256KB each
__device__ float g_hlast[BB * UU];
__device__ __align__(128) unsigned g_barcnt[32]; // arrival counter (own line)
__device__ __align__(128) unsigned g_epoch[32];  // epoch flag (own line)

// ---------------------------------------------------------------------------
// Helpers
// ---------------------------------------------------------------------------
__device__ __forceinline__ float cvt_tf32(float a) {
    float r;
    asm("cvt.rna.tf32.f32 %0, %1;" : "=f"(r) : "f"(a));
    return r;
}

__device__ __forceinline__ void cp16(void* s, const void* g) {
    uint32_t sa = (uint32_t)__cvta_generic_to_shared(s);
    asm volatile("cp.async.cg.shared.global [%0], [%1], 16;" :: "r"(sa), "l"(g));
}
#define CP_COMMIT()  asm volatile("cp.async.commit_group;" ::: "memory")
#define CP_WAIT(n)   asm volatile("cp.async.wait_group %0;" :: "n"(n) : "memory")

#define MMA_TF32(d, a, b0v, b1v) \
    asm volatile("mma.sync.aligned.m16n8k8.row.col.f32.tf32.tf32.f32 " \
        "{%0,%1,%2,%3}, {%4,%5,%6,%7}, {%8,%9}, {%0,%1,%2,%3};" \
        : "+f"((d)[0]), "+f"((d)[1]), "+f"((d)[2]), "+f"((d)[3]) \
        : "r"((a)[0]), "r"((a)[1]), "r"((a)[2]), "r"((a)[3]), \
          "r"(b0v), "r"(b1v))

// ===========================================================================
// Pack R^T (tf32-hi) into per-block A-frag layout (unchanged from R12).
// ===========================================================================
__global__ __launch_bounds__(256)
void pack_r3_kernel(const float* __restrict__ R, float* __restrict__ Rp)
{
    int i = blockIdx.x * blockDim.x + threadIdx.x;   // float4 index (2^20 total)
    int lane = i & 31;
    int mt   = (i >> 5) & 1;
    int kt   = (i >> 6) & 127;
    int b    = i >> 13;
    int g  = lane >> 2, ii = lane & 3;
    int m0 = mt * 16 + g, m1 = m0 + 8;
    int col0 = (m0 >> 3) * UU + b * 8 + (m0 & 7);
    int col1 = (m1 >> 3) * UU + b * 8 + (m1 & 7);
    int r0 = kt * 8 + ii;
    float4 o;
    o.x = cvt_tf32(__ldg(&R[(size_t)r0 * G4 + col0]));
    o.y = cvt_tf32(__ldg(&R[(size_t)r0 * G4 + col1]));
    o.z = cvt_tf32(__ldg(&R[(size_t)(r0 + 4) * G4 + col0]));
    o.w = cvt_tf32(__ldg(&R[(size_t)(r0 + 4) * G4 + col1]));
    *(float4*)&Rp[(size_t)i * 4] = o;
}

// ===========================================================================
// 2xTF32 GEMM (Ah*Bh + Ah*Bl), cp.async double-buffered (unchanged)
// ===========================================================================
#define GBK   32
#define A_LD  36
#define B_LD  136
#define ASZ   (128 * A_LD)
#define BSZ   (GBK * B_LD)
#define GEMM_SMEM_BYTES (2 * (ASZ + BSZ) * 4)   // 71680 B

__global__ __launch_bounds__(256, 2)
void gemm_tf32_kernel(const float* __restrict__ A, const float* __restrict__ W,
                      const float* __restrict__ bias, float* __restrict__ C,
                      int M, int N, int K)
{
    extern __shared__ float sm[];
    float* Asm[2] = { sm, sm + ASZ };
    float* Bsm[2] = { sm + 2 * ASZ, sm + 2 * ASZ + BSZ };

    const int tid  = threadIdx.x;
    const int m0   = blockIdx.y * 128;
    const int n0   = blockIdx.x * 128;
    const int lane = tid & 31, wid = tid >> 5;
    const int wm   = (wid & 3) * 32;
    const int wn   = (wid >> 2) * 64;
    const int g    = lane >> 2, ii = lane & 3;

    const int a_r = tid >> 3, a_c = (tid & 7) * 4;
    const int b_r = tid >> 5, b_c = (tid & 31) * 4;

    float acc[2][8][4];
    #pragma unroll
    for (int mi = 0; mi < 2; mi++)
        #pragma unroll
        for (int ni = 0; ni < 8; ni++)
            #pragma unroll
            for (int q = 0; q < 4; q++) acc[mi][ni][q] = 0.f;

    const int nk = K >> 5;

    {
        #pragma unroll
        for (int p = 0; p < 4; p++)
            cp16(&Asm[0][(a_r + p * 32) * A_LD + a_c],
                 &A[(size_t)(m0 + a_r + p * 32) * K + a_c]);
        #pragma unroll
        for (int p = 0; p < 4; p++)
            cp16(&Bsm[0][(b_r + p * 8) * B_LD + b_c],
                 &W[(size_t)(b_r + p * 8) * N + n0 + b_c]);
        CP_COMMIT();
    }

    for (int ch = 0; ch < nk; ch++) {
        const int buf = ch & 1;
        if (ch + 1 < nk) {
            const int k0 = (ch + 1) << 5;
            #pragma unroll
            for (int p = 0; p < 4; p++)
                cp16(&Asm[buf ^ 1][(a_r + p * 32) * A_LD + a_c],
                     &A[(size_t)(m0 + a_r + p * 32) * K + k0 + a_c]);
            #pragma unroll
            for (int p = 0; p < 4; p++)
                cp16(&Bsm[buf ^ 1][(b_r + p * 8) * B_LD + b_c],
                     &W[(size_t)(k0 + b_r + p * 8) * N + n0 + b_c]);
            CP_COMMIT();
            CP_WAIT(1);
        } else {
            CP_WAIT(0);
        }
        __syncthreads();

        const float* Ab = Asm[buf];
        const float* Bb = Bsm[buf];
        #pragma unroll
        for (int ks = 0; ks < 4; ks++) {
            const int kb = ks * 8;
            uint32_t ah[2][4];
            #pragma unroll
            for (int mi = 0; mi < 2; mi++) {
                int r0 = (wm + mi * 16 + g) * A_LD + kb + ii;
                int r8 = r0 + 8 * A_LD;
                ah[mi][0] = __float_as_uint(cvt_tf32(Ab[r0]));
                ah[mi][1] = __float_as_uint(cvt_tf32(Ab[r8]));
                ah[mi][2] = __float_as_uint(cvt_tf32(Ab[r0 + 4]));
                ah[mi][3] = __float_as_uint(cvt_tf32(Ab[r8 + 4]));
            }
            #pragma unroll
            for (int ni = 0; ni < 8; ni++) {
                int nb = wn + ni * 8 + g;
                float w0 = Bb[(kb + ii) * B_LD + nb];
                float w1 = Bb[(kb + ii + 4) * B_LD + nb];
                float bh0f = cvt_tf32(w0), bh1f = cvt_tf32(w1);
                uint32_t bh0 = __float_as_uint(bh0f);
                uint32_t bh1 = __float_as_uint(bh1f);
                uint32_t bl0 = __float_as_uint(cvt_tf32(w0 - bh0f));
                uint32_t bl1 = __float_as_uint(cvt_tf32(w1 - bh1f));
                #pragma unroll
                for (int mi = 0; mi < 2; mi++) {
                    MMA_TF32(acc[mi][ni], ah[mi], bh0, bh1);
                    MMA_TF32(acc[mi][ni], ah[mi], bl0, bl1);
                }
            }
        }
        __syncthreads();
    }

    #pragma unroll
    for (int mi = 0; mi < 2; mi++) {
        int r0 = m0 + wm + mi * 16 + g;
        #pragma unroll
        for (int ni = 0; ni < 8; ni++) {
            int cc = n0 + wn + ni * 8 + ii * 2;
            float b0v = __ldg(&bias[cc]);
            float b1v = __ldg(&bias[cc + 1]);
            float2 o0 = make_float2(acc[mi][ni][0] + b0v, acc[mi][ni][1] + b1v);
            float2 o1 = make_float2(acc[mi][ni][2] + b0v, acc[mi][ni][3] + b1v);
            *(float2*)&C[(size_t)r0 * N + cc] = o0;
            *(float2*)&C[(size_t)(r0 + 8) * N + cc] = o1;
        }
    }
}

// ===========================================================================
// Fast grid barrier
// ===========================================================================
__device__ __forceinline__ void grid_barrier_step(unsigned t1)
{
    __syncthreads();
    if (threadIdx.x == 0) {
        unsigned old;
        asm volatile("atom.release.gpu.global.add.u32 %0, [%1], %2;"
                     : "=r"(old) : "l"(&g_barcnt[0]), "r"(1u) : "memory");
        if (old + 1u == 128u * t1) {
            asm volatile("st.release.gpu.global.u32 [%0], %1;"
                         :: "l"(&g_epoch[0]), "r"(t1) : "memory");
        } else {
            unsigned e;
            do {
                __nanosleep(32);
                asm volatile("ld.acquire.gpu.global.u32 %0, [%1];"
                             : "=r"(e) : "l"(&g_epoch[0]) : "memory");
            } while (e < t1);
        }
    }
    __syncthreads();
}

// ===========================================================================
// Persistent LSTM layer — transposed recurrence z^T = R^T · h^T.
// 128 blocks x 512 threads (16 warps = 8 K-slices x 2 row-halves).
// Warp (ks, hf): kt in [16ks,16ks+16), nt in [4hf,4hf+4).
// A = R^T A-frags in smem (128 KB, once). B = h^T B-frags ldcg from L2.
// Two row-half warps of one K-slice write disjoint nt of the same zsum slot.
// 4 warps/SMSP for latency hiding; ~100 regs/thread.
// ===========================================================================
#define ZS_LD 72
#define LSTM_SMEM_BYTES ((32768 + 8 * 32 * ZS_LD) * 4)   // 204800 B

__global__ __launch_bounds__(512, 1)
void lstm_mma_kernel(const float* __restrict__ zx,     // [B*TT][G4], row=b*TT+t
                     const float* __restrict__ Rp,     // packed A-frags
                     float* __restrict__ hpH0, float* __restrict__ hpH1,
                     float* __restrict__ hseq,         // [B][TT][UU] or null
                     float* __restrict__ hlast)        // [B][UU] or null
{
    extern __shared__ float dsm[];
    float* Rs   = dsm;                     // 32768 floats
    float* zsum = dsm + 32768;             // 8*32*ZS_LD floats

    const int tid  = threadIdx.x;
    const int b    = blockIdx.x;           // 0..127
    const int u0   = b * 8;
    const int lane = tid & 31, wid = tid >> 5;
    const int ks   = wid & 7;              // K-slice
    const int hf   = wid >> 3;             // row half
    const int g    = lane >> 2, ii = lane & 3;
    const int lane4 = lane * 4;
    const int ksl  = ks * 16;              // ktile base
    const int ntb  = hf * 4;               // nt base

    // load this block's packed R (A-frags) into smem, once
    {
        const float4* src = (const float4*)(Rp + (size_t)b * 32768);
        float4* dst = (float4*)Rs;
        #pragma unroll
        for (int q = 0; q < 16; q++)
            dst[q * 512 + tid] = __ldg(&src[q * 512 + tid]);
    }
    __syncthreads();

    // gating ownership: ONE item per thread: (row, u0+j0)
    const int row = tid >> 3, j0 = tid & 7;
    float c = 0.f;

    // h^T B-frag write index (kt == b for this block's units)
    const int pw = ((b * 8 + (row >> 3)) * 32 + (row & 7) * 4 + (j0 & 3)) * 2 + (j0 >> 2);

    for (int t = 0; t < TT; t++) {
        const float* Ain  = (t & 1) ? hpH1 : hpH0;
        float*       Aout = (t & 1) ? hpH0 : hpH1;
        const float2* hp2 = (const float2*)Ain;

        // zx prefetch (gate inputs, independent of h)
        float zxv[4];
        {
            const float* z0 = zx + (size_t)row * (TT * G4) + (size_t)t * G4 + u0 + j0;
            #pragma unroll
            for (int q = 0; q < 4; q++) zxv[q] = __ldcs(z0 + q * UU);
        }

        float acc[2][4][4];
        #pragma unroll
        for (int mt = 0; mt < 2; mt++)
            #pragma unroll
            for (int nt = 0; nt < 4; nt++)
                #pragma unroll
                for (int q = 0; q < 4; q++) acc[mt][nt][q] = 0.f;

        // B-frag double buffer
        uint32_t bbuf[2][4][2];
        #pragma unroll
        for (int nt = 0; nt < 4; nt++) {
            float2 v = __ldcg(&hp2[(ksl * 8 + ntb + nt) * 32 + lane]);
            bbuf[0][nt][0] = __float_as_uint(v.x);
            bbuf[0][nt][1] = __float_as_uint(v.y);
        }

        #pragma unroll
        for (int kt = 0; kt < 16; kt++) {
            const int cur = kt & 1;
            if (kt < 15) {
                #pragma unroll
                for (int nt = 0; nt < 4; nt++) {
                    float2 v = __ldcg(&hp2[((ksl + kt + 1) * 8 + ntb + nt) * 32 + lane]);
                    bbuf[cur ^ 1][nt][0] = __float_as_uint(v.x);
                    bbuf[cur ^ 1][nt][1] = __float_as_uint(v.y);
                }
            }
            uint32_t a0[4], a1[4];
            *(float4*)a0 = *(const float4*)&Rs[((ksl + kt) * 2 + 0) * 128 + lane4];
            *(float4*)a1 = *(const float4*)&Rs[((ksl + kt) * 2 + 1) * 128 + lane4];
            #pragma unroll
            for (int nt = 0; nt < 4; nt++) {
                MMA_TF32(acc[0][nt], a0, bbuf[cur][nt][0], bbuf[cur][nt][1]);
                MMA_TF32(acc[1][nt], a1, bbuf[cur][nt][0], bbuf[cur][nt][1]);
            }
        }

        // store partial z^T: slot ks, rows m, cols ntb.. (disjoint between hf)
        #pragma unroll
        for (int mt = 0; mt < 2; mt++)
            #pragma unroll
            for (int nt = 0; nt < 4; nt++) {
                int off = (ks * 32 + mt * 16 + g) * ZS_LD + (ntb + nt) * 8 + ii * 2;
                *(float2*)&zsum[off] = make_float2(acc[mt][nt][0], acc[mt][nt][1]);
                *(float2*)&zsum[off + 8 * ZS_LD] = make_float2(acc[mt][nt][2], acc[mt][nt][3]);
            }
        __syncthreads();

        // reduce 8 K-slice partials for this thread's single gating item
        float z[4] = {0.f, 0.f, 0.f, 0.f};
        #pragma unroll
        for (int w = 0; w < 8; w++) {
            int base = w * 32 * ZS_LD + j0 * ZS_LD + row;
            #pragma unroll
            for (int gq = 0; gq < 4; gq++)
                z[gq] += zsum[base + gq * 8 * ZS_LD];
        }

        // gating (c in register); write h^T B-frag packed + exact hseq/hlast
        {
            int u = u0 + j0;
            float zi = z[0] + zxv[0];
            float zf = z[1] + zxv[1];
            float zg = z[2] + zxv[2];
            float zo = z[3] + zxv[3];
            float ig = 1.f / (1.f + __expf(-zi));
            float fg = 1.f / (1.f + __expf(-zf));
            float og = 1.f / (1.f + __expf(-zo));
            c = fmaf(fg, c, ig * zg);
            float hn = og * c;
            __stcg(&Aout[pw], cvt_tf32(hn));
            if (hseq) hseq[(size_t)row * (TT * UU) + (size_t)t * UU + u] = hn;
            if (hlast && t == TT - 1) hlast[row * UU + u] = hn;
        }

        if (t != TT - 1)
            grid_barrier_step((unsigned)(t + 1));
    }
}

// ===========================================================================
// LayerNorm + tanh
// ===========================================================================
__global__ __launch_bounds__(256, 4)
void ln_tanh_kernel(const float* __restrict__ in, float* __restrict__ out,
                    const float* __restrict__ gamma, const float* __restrict__ beta)
{
    const int row = blockIdx.x;
    const float* xr = in + (size_t)row * UU;
    float* yr = out + (size_t)row * UU;
    const int tid = threadIdx.x;

    float v[4];
    float s = 0.f, sq = 0.f;
    #pragma unroll
    for (int q = 0; q < 4; q++) {
        v[q] = xr[tid + q * 256];
        s += v[q];
        sq = fmaf(v[q], v[q], sq);
    }
    __shared__ float sm1[8], sm2[8];
    #pragma unroll
    for (int o = 16; o > 0; o >>= 1) {
        s  += __shfl_xor_sync(0xffffffffu, s, o);
        sq += __shfl_xor_sync(0xffffffffu, sq, o);
    }
    if ((tid & 31) == 0) { sm1[tid >> 5] = s; sm2[tid >> 5] = sq; }
    __syncthreads();
    __shared__ float s_mu, s_inv;
    if (tid == 0) {
        float ts = 0.f, tq = 0.f;
        #pragma unroll
        for (int w = 0; w < 8; w++) { ts += sm1[w]; tq += sm2[w]; }
        float mu = ts * (1.f / UU);
        float var = tq * (1.f / UU) - mu * mu;
        s_mu = mu;
        s_inv = rsqrtf(var + LN_EPS);
    }
    __syncthreads();
    float mu = s_mu, inv = s_inv;
    #pragma unroll
    for (int q = 0; q < 4; q++) {
        int idx = tid + q * 256;
        float y = (v[q] - mu) * inv * gamma[idx] + beta[idx];
        yr[idx] = tanhf(y);
    }
}

// ===========================================================================
// Per-layer init: zero packed h0 (ping), reset barrier counter + epoch
// ===========================================================================
__global__ void init_kernel(float* __restrict__ hH)
{
    int i = blockIdx.x * blockDim.x + threadIdx.x;
    if (i == 0) { g_barcnt[0] = 0u; g_epoch[0] = 0u; }
    if (i < 128 * 8 * 32 * 2) hH[i] = 0.f;
}

// ===========================================================================
// Launch: 10 graph nodes.  Order per layer: pack, init, gemm, lstm, ln
// ===========================================================================
extern "C" void kernel_launch(void* const* d_in, const int* in_sizes, int n_in,
                              void* d_out, int out_size)
{
    const float* x      = (const float*)d_in[0];
    const float* W1     = (const float*)d_in[1];
    const float* R1     = (const float*)d_in[2];
    const float* b1     = (const float*)d_in[3];
    const float* gamma1 = (const float*)d_in[4];
    const float* beta1  = (const float*)d_in[5];
    const float* W2     = (const float*)d_in[6];
    const float* R2     = (const float*)d_in[7];
    const float* b2     = (const float*)d_in[8];
    const float* gamma2 = (const float*)d_in[9];
    const float* beta2  = (const float*)d_in[10];
    float* out = (float*)d_out;

    float *zx, *hseq, *rp, *hpH0, *hpH1, *hlast;
    cudaGetSymbolAddress((void**)&zx,    g_zx);
    cudaGetSymbolAddress((void**)&hseq,  g_hseq);
    cudaGetSymbolAddress((void**)&rp,    g_rp2);
    cudaGetSymbolAddress((void**)&hlast, g_hlast);
    { void* p; cudaGetSymbolAddress(&p, g_hp_hi); hpH0 = (float*)p; hpH1 = hpH0 + 128 * 8 * 32 * 2; }

    cudaFuncSetAttribute(gemm_tf32_kernel,
                         cudaFuncAttributeMaxDynamicSharedMemorySize, GEMM_SMEM_BYTES);
    cudaFuncSetAttribute(lstm_mma_kernel,
                         cudaFuncAttributeMaxDynamicSharedMemorySize, LSTM_SMEM_BYTES);

    const int M = BB * TT;                       // 32768
    const dim3 ggrid(G4 / 128, M / 128);         // (32, 256)
    const int initg = (128 * 8 * 32 * 2 + 255) / 256;
    const int packg = (128 * 128 * 2 * 32) / 256;

    // ---- Layer 1 ----
    pack_r3_kernel<<<packg, 256>>>(R1, rp);
    init_kernel<<<initg, 256>>>(hpH0);
    gemm_tf32_kernel<<<ggrid, 256, GEMM_SMEM_BYTES>>>(x, W1, b1, zx, M, G4, DD);
    lstm_mma_kernel<<<128, 512, LSTM_SMEM_BYTES>>>(zx, rp, hpH0, hpH1, hseq, (float*)nullptr);
    ln_tanh_kernel<<<M, 256>>>(hseq, hseq, gamma1, beta1);

    // ---- Layer 2 ----
    pack_r3_kernel<<<packg, 256>>>(R2, rp);
    init_kernel<<<initg, 256>>>(hpH0);
    gemm_tf32_kernel<<<ggrid, 256, GEMM_SMEM_BYTES>>>(hseq, W2, b2, zx, M, G4, UU);
    lstm_mma_kernel<<<128, 512, LSTM_SMEM_BYTES>>>(zx, rp, hpH0, hpH1, (float*)nullptr, hlast);
    ln_tanh_kernel<<<BB, 256>>>(hlast, out, gamma2, beta2);
}